// round 1
// baseline (speedup 1.0000x reference)
#include <cuda_runtime.h>
#include <cstdint>

// Problem constants (fixed by the reference setup_inputs).
#define NTOT 16384
#define FEAT 256
#define EMB  100
#define PTS_P 128

// Scratch (device globals — no runtime allocation allowed).
__device__ float g_y1[NTOT * FEAT];    // relu(X@sg_w1+b1), structure order
__device__ float g_y2[NTOT * FEAT];    // y1@sg_w2+b2
__device__ float g_feat[NTOT * 256];   // pointnet pooled features

// ---------------------------------------------------------------------------
// Generic 64x64-tile fp32 GEMM: C[m, coff+n] = (relu?)(A@B + bias)
// A is MxK row-major (or gathered from src/ref per the structure permutation),
// B is KxN row-major. 256 threads, per-thread 4x4 tile, BK=16.
// ---------------------------------------------------------------------------
template <bool GATHER, bool RELU>
__global__ __launch_bounds__(256) void gemm64_kernel(
    const float* __restrict__ A,
    const float* __restrict__ Asrc,
    const float* __restrict__ Aref,
    const float* __restrict__ B,
    const float* __restrict__ bias,
    float* __restrict__ C,
    int M, int N, int K, int ldc, int coff)
{
    __shared__ float As[16][72];   // [k][m], padded for alignment
    __shared__ float Bs[16][64];   // [k][n]

    const int tid = threadIdx.x;
    const int m0 = blockIdx.y * 64;
    const int n0 = blockIdx.x * 64;

    const int ty = tid >> 4;       // 0..15 -> rows m0 + ty*4 ..
    const int tx = tid & 15;       // 0..15 -> cols n0 + tx*4 ..

    // A loader mapping: each thread loads one float4 along K
    const int lrow = tid >> 2;          // 0..63
    const int lkq  = (tid & 3) * 4;     // 0,4,8,12
    const float* arow;
    if (GATHER) {
        const int n = m0 + lrow;
        const int b = n >> 10;
        const int j = n & 1023;
        arow = (j < 512) ? (Asrc + (size_t)(b * 512 + j) * K)
                         : (Aref + (size_t)(b * 512 + (j - 512)) * K);
    } else {
        arow = A + (size_t)(m0 + lrow) * K;
    }
    // B loader mapping
    const int brow = tid >> 4;          // 0..15
    const int bn   = (tid & 15) * 4;    // 0..60

    float acc[4][4] = {};

    for (int k0 = 0; k0 < K; k0 += 16) {
        // Load A tile (transposed into SMEM)
        float4 av = *reinterpret_cast<const float4*>(arow + k0 + lkq);
        As[lkq + 0][lrow] = av.x;
        As[lkq + 1][lrow] = av.y;
        As[lkq + 2][lrow] = av.z;
        As[lkq + 3][lrow] = av.w;

        // Load B tile (with N-tail guard; rows of se_w/oe_w are 400B = 16B multiple)
        float4 bv;
        const int nbase = n0 + bn;
        if (nbase + 3 < N) {
            bv = *reinterpret_cast<const float4*>(B + (size_t)(k0 + brow) * N + nbase);
        } else {
            bv.x = (nbase + 0 < N) ? B[(size_t)(k0 + brow) * N + nbase + 0] : 0.f;
            bv.y = (nbase + 1 < N) ? B[(size_t)(k0 + brow) * N + nbase + 1] : 0.f;
            bv.z = (nbase + 2 < N) ? B[(size_t)(k0 + brow) * N + nbase + 2] : 0.f;
            bv.w = (nbase + 3 < N) ? B[(size_t)(k0 + brow) * N + nbase + 3] : 0.f;
        }
        *reinterpret_cast<float4*>(&Bs[brow][bn]) = bv;

        __syncthreads();

        #pragma unroll
        for (int kk = 0; kk < 16; kk++) {
            float4 a = *reinterpret_cast<float4*>(&As[kk][ty * 4]);
            float4 b = *reinterpret_cast<float4*>(&Bs[kk][tx * 4]);
            acc[0][0] = fmaf(a.x, b.x, acc[0][0]);
            acc[0][1] = fmaf(a.x, b.y, acc[0][1]);
            acc[0][2] = fmaf(a.x, b.z, acc[0][2]);
            acc[0][3] = fmaf(a.x, b.w, acc[0][3]);
            acc[1][0] = fmaf(a.y, b.x, acc[1][0]);
            acc[1][1] = fmaf(a.y, b.y, acc[1][1]);
            acc[1][2] = fmaf(a.y, b.z, acc[1][2]);
            acc[1][3] = fmaf(a.y, b.w, acc[1][3]);
            acc[2][0] = fmaf(a.z, b.x, acc[2][0]);
            acc[2][1] = fmaf(a.z, b.y, acc[2][1]);
            acc[2][2] = fmaf(a.z, b.z, acc[2][2]);
            acc[2][3] = fmaf(a.z, b.w, acc[2][3]);
            acc[3][0] = fmaf(a.w, b.x, acc[3][0]);
            acc[3][1] = fmaf(a.w, b.y, acc[3][1]);
            acc[3][2] = fmaf(a.w, b.z, acc[3][2]);
            acc[3][3] = fmaf(a.w, b.w, acc[3][3]);
        }
        __syncthreads();
    }

    // Epilogue
    #pragma unroll
    for (int i = 0; i < 4; i++) {
        const int m = m0 + ty * 4 + i;
        #pragma unroll
        for (int j = 0; j < 4; j++) {
            const int n = n0 + tx * 4 + j;
            if (n < N) {
                float v = acc[i][j] + bias[n];
                if (RELU) v = fmaxf(v, 0.f);
                C[(size_t)m * ldc + coff + n] = v;
            }
        }
    }
}

// ---------------------------------------------------------------------------
// Fused per-object PointNet: pts(128x3) -> relu(@W1+b1) -> relu(@W2+b2)
// -> @W3 -> column-max over the 128 points -> +b3 -> g_feat[obj][256].
// 512 threads. SMEM: W3(128KB) + W2(32KB, aliased by max-partials) +
// H2(64KB) + pts + W1/b1 = 231,936 B.
// ---------------------------------------------------------------------------
#define OPB 4   // objects per block

__global__ __launch_bounds__(512) void pointnet_kernel(
    const float* __restrict__ pts,   // [16384][128][3]
    const float* __restrict__ w1,    // [3][64]
    const float* __restrict__ b1,    // [64]
    const float* __restrict__ w2,    // [64][128]
    const float* __restrict__ b2,    // [128]
    const float* __restrict__ w3,    // [128][256]
    const float* __restrict__ b3,    // [256]
    float* __restrict__ feat_out)    // [16384][256]
{
    extern __shared__ float smem[];
    float* sW3  = smem;                     // 128*256
    float* sW2  = sW3 + 128 * 256;          // 64*128 (aliased: sPart[16][256])
    float* sH2  = sW2 + 64 * 128;           // 128*128  (H2[p][j])
    float* sPts = sH2 + 128 * 128;          // 128*3
    float* sW1  = sPts + 128 * 3;           // 3*64
    float* sB1  = sW1 + 3 * 64;             // 64

    const int tid = threadIdx.x;

    // Persistent weights: W3, W1, b1 (loaded once per block)
    for (int i = tid; i < 128 * 256 / 4; i += 512)
        reinterpret_cast<float4*>(sW3)[i] = reinterpret_cast<const float4*>(w3)[i];
    for (int i = tid; i < 192; i += 512) sW1[i] = w1[i];
    if (tid < 64) sB1[tid] = b1[tid];

    const int obj0 = blockIdx.x * OPB;

    for (int t = 0; t < OPB; ++t) {
        const int obj = obj0 + t;

        // Reload W2 (its region is clobbered by the max-partials each object)
        for (int i = tid; i < 64 * 128 / 4; i += 512)
            reinterpret_cast<float4*>(sW2)[i] = reinterpret_cast<const float4*>(w2)[i];
        // Stage points
        const float* po = pts + (size_t)obj * (PTS_P * 3);
        for (int i = tid; i < PTS_P * 3; i += 512) sPts[i] = po[i];
        __syncthreads();

        // ---- Phase 1: H2[p][j] = relu( relu(pts@W1+b1) @ W2 + b2 ), H1 on the fly
        {
            const int ty = tid >> 4;        // 0..31, rows r0=ty*4
            const int tx = tid & 15;        // cols: lo = tx*4, hi = 64+tx*4
            const int r0 = ty * 4;
            float px[4][3];
            #pragma unroll
            for (int rr = 0; rr < 4; rr++) {
                px[rr][0] = sPts[(r0 + rr) * 3 + 0];
                px[rr][1] = sPts[(r0 + rr) * 3 + 1];
                px[rr][2] = sPts[(r0 + rr) * 3 + 2];
            }
            float acc[4][8] = {};
            #pragma unroll 4
            for (int k = 0; k < 64; k++) {
                const float w0 = sW1[k], wa = sW1[64 + k], wb = sW1[128 + k], bk = sB1[k];
                float a[4];
                #pragma unroll
                for (int rr = 0; rr < 4; rr++) {
                    float h = fmaf(px[rr][2], wb, fmaf(px[rr][1], wa, fmaf(px[rr][0], w0, bk)));
                    a[rr] = fmaxf(h, 0.f);
                }
                const float4 bl = *reinterpret_cast<const float4*>(&sW2[k * 128 + tx * 4]);
                const float4 bh = *reinterpret_cast<const float4*>(&sW2[k * 128 + 64 + tx * 4]);
                #pragma unroll
                for (int rr = 0; rr < 4; rr++) {
                    acc[rr][0] = fmaf(a[rr], bl.x, acc[rr][0]);
                    acc[rr][1] = fmaf(a[rr], bl.y, acc[rr][1]);
                    acc[rr][2] = fmaf(a[rr], bl.z, acc[rr][2]);
                    acc[rr][3] = fmaf(a[rr], bl.w, acc[rr][3]);
                    acc[rr][4] = fmaf(a[rr], bh.x, acc[rr][4]);
                    acc[rr][5] = fmaf(a[rr], bh.y, acc[rr][5]);
                    acc[rr][6] = fmaf(a[rr], bh.z, acc[rr][6]);
                    acc[rr][7] = fmaf(a[rr], bh.w, acc[rr][7]);
                }
            }
            const float4 b2l = *reinterpret_cast<const float4*>(&b2[tx * 4]);
            const float4 b2h = *reinterpret_cast<const float4*>(&b2[64 + tx * 4]);
            #pragma unroll
            for (int rr = 0; rr < 4; rr++) {
                float4 v, w;
                v.x = fmaxf(acc[rr][0] + b2l.x, 0.f);
                v.y = fmaxf(acc[rr][1] + b2l.y, 0.f);
                v.z = fmaxf(acc[rr][2] + b2l.z, 0.f);
                v.w = fmaxf(acc[rr][3] + b2l.w, 0.f);
                w.x = fmaxf(acc[rr][4] + b2h.x, 0.f);
                w.y = fmaxf(acc[rr][5] + b2h.y, 0.f);
                w.z = fmaxf(acc[rr][6] + b2h.z, 0.f);
                w.w = fmaxf(acc[rr][7] + b2h.w, 0.f);
                *reinterpret_cast<float4*>(&sH2[(r0 + rr) * 128 + tx * 4]) = v;
                *reinterpret_cast<float4*>(&sH2[(r0 + rr) * 128 + 64 + tx * 4]) = w;
            }
        }
        __syncthreads();

        // ---- Phase 2: H3 = H2 @ W3 ; colmax over the 128 rows ; +b3
        {
            const int ty = tid >> 5;        // 0..15, rows r0=ty*8 (warp-uniform -> broadcast A)
            const int tx = tid & 31;        // cols: lo = tx*4, hi = 128+tx*4
            const int r0 = ty * 8;
            float acc[8][8] = {};
            #pragma unroll 2
            for (int k = 0; k < 128; k++) {
                float a[8];
                #pragma unroll
                for (int rr = 0; rr < 8; rr++) a[rr] = sH2[(r0 + rr) * 128 + k];
                const float4 bl = *reinterpret_cast<const float4*>(&sW3[k * 256 + tx * 4]);
                const float4 bh = *reinterpret_cast<const float4*>(&sW3[k * 256 + 128 + tx * 4]);
                #pragma unroll
                for (int rr = 0; rr < 8; rr++) {
                    acc[rr][0] = fmaf(a[rr], bl.x, acc[rr][0]);
                    acc[rr][1] = fmaf(a[rr], bl.y, acc[rr][1]);
                    acc[rr][2] = fmaf(a[rr], bl.z, acc[rr][2]);
                    acc[rr][3] = fmaf(a[rr], bl.w, acc[rr][3]);
                    acc[rr][4] = fmaf(a[rr], bh.x, acc[rr][4]);
                    acc[rr][5] = fmaf(a[rr], bh.y, acc[rr][5]);
                    acc[rr][6] = fmaf(a[rr], bh.z, acc[rr][6]);
                    acc[rr][7] = fmaf(a[rr], bh.w, acc[rr][7]);
                }
            }
            // per-thread column max over its 8 rows
            float m[8];
            #pragma unroll
            for (int cc = 0; cc < 8; cc++) {
                float v = acc[0][cc];
                #pragma unroll
                for (int rr = 1; rr < 8; rr++) v = fmaxf(v, acc[rr][cc]);
                m[cc] = v;
            }
            // cross-row-group reduce via partials in the (now idle) W2 region
            float* sPart = sW2;             // [16][256]
            *reinterpret_cast<float4*>(&sPart[ty * 256 + tx * 4]) =
                make_float4(m[0], m[1], m[2], m[3]);
            *reinterpret_cast<float4*>(&sPart[ty * 256 + 128 + tx * 4]) =
                make_float4(m[4], m[5], m[6], m[7]);
            __syncthreads();
            if (tid < 256) {
                float v = sPart[tid];
                #pragma unroll
                for (int g = 1; g < 16; g++) v = fmaxf(v, sPart[g * 256 + tid]);
                feat_out[(size_t)obj * 256 + tid] = v + b3[tid];
            }
            __syncthreads();   // protect sPart/sH2/sPts before next object
        }
    }
}

// ---------------------------------------------------------------------------
// Launch
// ---------------------------------------------------------------------------
extern "C" void kernel_launch(void* const* d_in, const int* in_sizes, int n_in,
                              void* d_out, int out_size)
{
    const float* tot_obj_pts = (const float*)d_in[0];
    const float* src_feat    = (const float*)d_in[1];
    const float* ref_feat    = (const float*)d_in[2];
    // d_in[3] graph_per_obj_count (constant 512/512), d_in[4] overlap,
    // d_in[5] target: unused by the forward computation.
    const float* sg_w1 = (const float*)d_in[6];
    const float* sg_b1 = (const float*)d_in[7];
    const float* sg_w2 = (const float*)d_in[8];
    const float* sg_b2 = (const float*)d_in[9];
    const float* se_w  = (const float*)d_in[10];
    const float* se_b  = (const float*)d_in[11];
    const float* p_w1  = (const float*)d_in[12];
    const float* p_b1  = (const float*)d_in[13];
    const float* p_w2  = (const float*)d_in[14];
    const float* p_b2  = (const float*)d_in[15];
    const float* p_w3  = (const float*)d_in[16];
    const float* p_b3  = (const float*)d_in[17];
    const float* oe_w  = (const float*)d_in[18];
    const float* oe_b  = (const float*)d_in[19];
    float* out = (float*)d_out;

    void *py1, *py2, *pfeat;
    cudaGetSymbolAddress(&py1, g_y1);
    cudaGetSymbolAddress(&py2, g_y2);
    cudaGetSymbolAddress(&pfeat, g_feat);
    float* y1 = (float*)py1;
    float* y2 = (float*)py2;
    float* feat = (float*)pfeat;

    const int SMEM_BYTES =
        (128 * 256 + 64 * 128 + 128 * 128 + 128 * 3 + 3 * 64 + 64) * 4; // 231936
    cudaFuncSetAttribute(pointnet_kernel,
                         cudaFuncAttributeMaxDynamicSharedMemorySize, SMEM_BYTES);

    // PointNet branch (dominant)
    pointnet_kernel<<<NTOT / OPB, 512, SMEM_BYTES>>>(
        tot_obj_pts, p_w1, p_b1, p_w2, p_b2, p_w3, p_b3, feat);

    // sgnet chain (gather = structure permutation fused into stage 1)
    {
        dim3 grid(256 / 64, NTOT / 64);
        gemm64_kernel<true, true><<<grid, 256>>>(
            nullptr, src_feat, ref_feat, sg_w1, sg_b1, y1,
            NTOT, 256, 256, 256, 0);
        gemm64_kernel<false, false><<<grid, 256>>>(
            y1, nullptr, nullptr, sg_w2, sg_b2, y2,
            NTOT, 256, 256, 256, 0);
    }
    {
        dim3 grid((EMB + 63) / 64, NTOT / 64);
        gemm64_kernel<false, false><<<grid, 256>>>(
            y2, nullptr, nullptr, se_w, se_b, out,
            NTOT, EMB, 256, 200, 0);
        gemm64_kernel<false, false><<<grid, 256>>>(
            feat, nullptr, nullptr, oe_w, oe_b, out,
            NTOT, EMB, 256, 200, 100);
    }
}

// round 3
// speedup vs baseline: 4.7938x; 4.7938x over previous
#include <cuda_runtime.h>
#include <cuda_fp16.h>
#include <cstdint>

#define NTOT 16384
#define EMB  100

// Scratch (device globals — no runtime allocation allowed).
__device__ float g_y1[NTOT * 256];
__device__ float g_y2[NTOT * 256];
__device__ float g_feat[NTOT * 256];

// ============================== helpers ==============================
__device__ __forceinline__ uint32_t smem_u32(const void* p) {
    uint32_t a;
    asm("{ .reg .u64 t; cvta.to.shared.u64 t, %1; cvt.u32.u64 %0, t; }"
        : "=r"(a) : "l"(p));
    return a;
}
__device__ __forceinline__ uint32_t pack2(float lo, float hi) {
    __half2 h = __floats2half2_rn(lo, hi);
    return *reinterpret_cast<uint32_t*>(&h);
}
__device__ __forceinline__ void ldsm_x4(uint32_t& r0, uint32_t& r1, uint32_t& r2, uint32_t& r3,
                                        uint32_t addr) {
    asm volatile("ldmatrix.sync.aligned.m8n8.x4.shared.b16 {%0,%1,%2,%3}, [%4];"
                 : "=r"(r0), "=r"(r1), "=r"(r2), "=r"(r3) : "r"(addr));
}
__device__ __forceinline__ void ldsm_x2t(uint32_t& r0, uint32_t& r1, uint32_t addr) {
    asm volatile("ldmatrix.sync.aligned.m8n8.x2.trans.shared.b16 {%0,%1}, [%2];"
                 : "=r"(r0), "=r"(r1) : "r"(addr));
}
__device__ __forceinline__ void mma16816(float* c, const uint32_t* a, uint32_t b0, uint32_t b1) {
    asm volatile("mma.sync.aligned.m16n8k16.row.col.f32.f16.f16.f32 "
                 "{%0,%1,%2,%3}, {%4,%5,%6,%7}, {%8,%9}, {%0,%1,%2,%3};"
                 : "+f"(c[0]), "+f"(c[1]), "+f"(c[2]), "+f"(c[3])
                 : "r"(a[0]), "r"(a[1]), "r"(a[2]), "r"(a[3]), "r"(b0), "r"(b1));
}

// SMEM byte offsets
#define SM_W3   0        /* 128 x 512B  (f16, swizzled)  = 65536 */
#define SM_W2   65536    /* 64  x 256B                    = 16384 */
#define SM_H2   81920    /* 128 x 256B                    = 32768 */
#define SM_H1   114688   /* 128 x 128B                    = 16384 */
#define SM_PART 131072   /* 4 x 256 f32                   = 4096  */
#define SM_B2   135168   /* 128 f32 */
#define SM_B3   135680   /* 256 f32 */
#define SM_W1   136704   /* 192 f32 */
#define SM_B1   137472   /* 64  f32 */
#define SM_TOTAL 137728

// ============================== PointNet (mma.sync f16) ==============================
__global__ __launch_bounds__(512, 1) void pointnet_mma(
    const float* __restrict__ pts,
    const float* __restrict__ w1, const float* __restrict__ b1,
    const float* __restrict__ w2, const float* __restrict__ b2,
    const float* __restrict__ w3, const float* __restrict__ b3,
    float* __restrict__ feat_out, int ntot)
{
    extern __shared__ char sm[];
    const uint32_t s0 = smem_u32(sm);
    const int tid = threadIdx.x;
    const int wid = tid >> 5, lane = tid & 31;

    // ---- Stage weights (once per block) ----
    // W3: [k=128][n=256] f32 -> f16, rowBytes=512, chunk(n/8) ^ (k&7)
    for (int i = tid * 8; i < 128 * 256; i += 512 * 8) {
        int k = i >> 8, n = i & 255;
        float4 f0 = *reinterpret_cast<const float4*>(w3 + i);
        float4 f1 = *reinterpret_cast<const float4*>(w3 + i + 4);
        uint4 u = make_uint4(pack2(f0.x, f0.y), pack2(f0.z, f0.w),
                             pack2(f1.x, f1.y), pack2(f1.z, f1.w));
        int ch = (n >> 3) ^ (k & 7);
        *reinterpret_cast<uint4*>(sm + SM_W3 + k * 512 + ch * 16) = u;
    }
    // W2: [k=64][n=128], rowBytes=256
    for (int i = tid * 8; i < 64 * 128; i += 512 * 8) {
        int k = i >> 7, n = i & 127;
        float4 f0 = *reinterpret_cast<const float4*>(w2 + i);
        float4 f1 = *reinterpret_cast<const float4*>(w2 + i + 4);
        uint4 u = make_uint4(pack2(f0.x, f0.y), pack2(f0.z, f0.w),
                             pack2(f1.x, f1.y), pack2(f1.z, f1.w));
        int ch = (n >> 3) ^ (k & 7);
        *reinterpret_cast<uint4*>(sm + SM_W2 + k * 256 + ch * 16) = u;
    }
    if (tid < 128) reinterpret_cast<float*>(sm + SM_B2)[tid] = b2[tid];
    if (tid < 256) reinterpret_cast<float*>(sm + SM_B3)[tid] = b3[tid];
    if (tid < 192) reinterpret_cast<float*>(sm + SM_W1)[tid] = w1[tid];
    if (tid < 64)  reinterpret_cast<float*>(sm + SM_B1)[tid] = b1[tid];
    __syncthreads();

    const float* sW1f = reinterpret_cast<const float*>(sm + SM_W1);
    const float* sB1f = reinterpret_cast<const float*>(sm + SM_B1);
    const float* sB2f = reinterpret_cast<const float*>(sm + SM_B2);
    const float* sB3f = reinterpret_cast<const float*>(sm + SM_B3);
    float* sPart = reinterpret_cast<float*>(sm + SM_PART);

    const int g = lane >> 2, tig = lane & 3;
    const int rt = wid >> 2, ct = wid & 3;
    const int r0 = rt * 32;

    for (int obj = blockIdx.x; obj < ntot; obj += gridDim.x) {
        // ---- H1 = relu(pts@W1 + b1) -> sH1 (f16, swizzled) ----
        {
            const int row = tid >> 2, q = tid & 3;
            const float* pr = pts + (size_t)obj * 384 + row * 3;
            const float x0 = pr[0], x1 = pr[1], x2 = pr[2];
            uint32_t u[8];
            #pragma unroll
            for (int e = 0; e < 8; e++) {
                const int c0 = q * 16 + e * 2;
                float v0 = fmaf(x2, sW1f[128 + c0],
                           fmaf(x1, sW1f[64 + c0], fmaf(x0, sW1f[c0], sB1f[c0])));
                float v1 = fmaf(x2, sW1f[129 + c0],
                           fmaf(x1, sW1f[65 + c0], fmaf(x0, sW1f[c0 + 1], sB1f[c0 + 1])));
                u[e] = pack2(fmaxf(v0, 0.f), fmaxf(v1, 0.f));
            }
            const int ch0 = (q * 2) ^ (row & 7), ch1 = (q * 2 + 1) ^ (row & 7);
            *reinterpret_cast<uint4*>(sm + SM_H1 + row * 128 + ch0 * 16) =
                make_uint4(u[0], u[1], u[2], u[3]);
            *reinterpret_cast<uint4*>(sm + SM_H1 + row * 128 + ch1 * 16) =
                make_uint4(u[4], u[5], u[6], u[7]);
        }
        __syncthreads();

        // ---- Phase 1: H2 = relu(H1 @ W2 + b2), warp tile 32x32 ----
        {
            const int n0 = ct * 32;
            uint32_t a[2][4][4];
            #pragma unroll
            for (int rg = 0; rg < 2; rg++)
                #pragma unroll
                for (int kb = 0; kb < 4; kb++) {
                    const int row = r0 + rg * 16 + (lane & 15);
                    const int ch = (kb * 2 + (lane >> 4)) ^ (row & 7);
                    ldsm_x4(a[rg][kb][0], a[rg][kb][1], a[rg][kb][2], a[rg][kb][3],
                            s0 + SM_H1 + row * 128 + ch * 16);
                }
            float c[2][4][4] = {};
            #pragma unroll
            for (int nb = 0; nb < 4; nb++) {
                const int nch = (n0 >> 3) + nb;
                #pragma unroll
                for (int kb = 0; kb < 4; kb++) {
                    const int krow = kb * 16 + (lane & 15);
                    uint32_t b0, b1;
                    ldsm_x2t(b0, b1, s0 + SM_W2 + krow * 256 + ((nch ^ (krow & 7)) * 16));
                    mma16816(c[0][nb], a[0][kb], b0, b1);
                    mma16816(c[1][nb], a[1][kb], b0, b1);
                }
            }
            #pragma unroll
            for (int rg = 0; rg < 2; rg++) {
                const int rowa = r0 + rg * 16 + g, rowb = rowa + 8;
                #pragma unroll
                for (int nb = 0; nb < 4; nb++) {
                    const int col = n0 + nb * 8 + 2 * tig;
                    const float bb0 = sB2f[col], bb1 = sB2f[col + 1];
                    const uint32_t p0 = pack2(fmaxf(c[rg][nb][0] + bb0, 0.f),
                                              fmaxf(c[rg][nb][1] + bb1, 0.f));
                    const uint32_t p1 = pack2(fmaxf(c[rg][nb][2] + bb0, 0.f),
                                              fmaxf(c[rg][nb][3] + bb1, 0.f));
                    const int nch = (n0 >> 3) + nb;
                    *reinterpret_cast<uint32_t*>(
                        sm + SM_H2 + rowa * 256 + ((nch ^ (rowa & 7)) * 16) + tig * 4) = p0;
                    *reinterpret_cast<uint32_t*>(
                        sm + SM_H2 + rowb * 256 + ((nch ^ (rowb & 7)) * 16) + tig * 4) = p1;
                }
            }
        }
        __syncthreads();

        // ---- Phase 2: H3 = H2 @ W3, fused column-max ----
        {
            uint32_t a[2][8][4];
            #pragma unroll
            for (int rg = 0; rg < 2; rg++)
                #pragma unroll
                for (int kb = 0; kb < 8; kb++) {
                    const int row = r0 + rg * 16 + (lane & 15);
                    const int ch = (kb * 2 + (lane >> 4)) ^ (row & 7);
                    ldsm_x4(a[rg][kb][0], a[rg][kb][1], a[rg][kb][2], a[rg][kb][3],
                            s0 + SM_H2 + row * 256 + ch * 16);
                }
            #pragma unroll
            for (int tile = 0; tile < 2; tile++) {
                const int n0 = ct * 32 + tile * 128;
                float c[2][4][4] = {};
                #pragma unroll
                for (int nb = 0; nb < 4; nb++) {
                    const int nch = (n0 >> 3) + nb;
                    #pragma unroll
                    for (int kb = 0; kb < 8; kb++) {
                        const int krow = kb * 16 + (lane & 15);
                        uint32_t b0, b1;
                        ldsm_x2t(b0, b1, s0 + SM_W3 + krow * 512 + ((nch ^ (krow & 7)) * 16));
                        mma16816(c[0][nb], a[0][kb], b0, b1);
                        mma16816(c[1][nb], a[1][kb], b0, b1);
                    }
                }
                #pragma unroll
                for (int nb = 0; nb < 4; nb++) {
                    float m0 = fmaxf(fmaxf(c[0][nb][0], c[0][nb][2]),
                                     fmaxf(c[1][nb][0], c[1][nb][2]));
                    float m1 = fmaxf(fmaxf(c[0][nb][1], c[0][nb][3]),
                                     fmaxf(c[1][nb][1], c[1][nb][3]));
                    #pragma unroll
                    for (int off = 4; off < 32; off <<= 1) {
                        m0 = fmaxf(m0, __shfl_xor_sync(0xffffffff, m0, off));
                        m1 = fmaxf(m1, __shfl_xor_sync(0xffffffff, m1, off));
                    }
                    if (lane < 4) {
                        sPart[rt * 256 + n0 + nb * 8 + 2 * tig]     = m0;
                        sPart[rt * 256 + n0 + nb * 8 + 2 * tig + 1] = m1;
                    }
                }
            }
        }
        __syncthreads();

        if (tid < 256) {
            const float v = fmaxf(fmaxf(sPart[tid], sPart[256 + tid]),
                                  fmaxf(sPart[512 + tid], sPart[768 + tid]));
            feat_out[(size_t)obj * 256 + tid] = v + sB3f[tid];
        }
        __syncthreads();
    }
}

// ============================== sgnet GEMMs (fp32, unchanged) ==============================
template <bool GATHER, bool RELU>
__global__ __launch_bounds__(256) void gemm64_kernel(
    const float* __restrict__ A, const float* __restrict__ Asrc, const float* __restrict__ Aref,
    const float* __restrict__ B, const float* __restrict__ bias, float* __restrict__ C,
    int M, int N, int K, int ldc, int coff)
{
    __shared__ float As[16][72];
    __shared__ float Bs[16][64];
    const int tid = threadIdx.x;
    const int m0 = blockIdx.y * 64, n0 = blockIdx.x * 64;
    const int ty = tid >> 4, tx = tid & 15;
    const int lrow = tid >> 2, lkq = (tid & 3) * 4;
    const float* arow;
    if (GATHER) {
        const int n = m0 + lrow, b = n >> 10, j = n & 1023;
        arow = (j < 512) ? (Asrc + (size_t)(b * 512 + j) * K)
                         : (Aref + (size_t)(b * 512 + (j - 512)) * K);
    } else {
        arow = A + (size_t)(m0 + lrow) * K;
    }
    const int brow = tid >> 4, bn = (tid & 15) * 4;
    float acc[4][4] = {};
    for (int k0 = 0; k0 < K; k0 += 16) {
        float4 av = *reinterpret_cast<const float4*>(arow + k0 + lkq);
        As[lkq + 0][lrow] = av.x; As[lkq + 1][lrow] = av.y;
        As[lkq + 2][lrow] = av.z; As[lkq + 3][lrow] = av.w;
        float4 bv;
        const int nbase = n0 + bn;
        if (nbase + 3 < N) {
            bv = *reinterpret_cast<const float4*>(B + (size_t)(k0 + brow) * N + nbase);
        } else {
            bv.x = (nbase + 0 < N) ? B[(size_t)(k0 + brow) * N + nbase + 0] : 0.f;
            bv.y = (nbase + 1 < N) ? B[(size_t)(k0 + brow) * N + nbase + 1] : 0.f;
            bv.z = (nbase + 2 < N) ? B[(size_t)(k0 + brow) * N + nbase + 2] : 0.f;
            bv.w = (nbase + 3 < N) ? B[(size_t)(k0 + brow) * N + nbase + 3] : 0.f;
        }
        *reinterpret_cast<float4*>(&Bs[brow][bn]) = bv;
        __syncthreads();
        #pragma unroll
        for (int kk = 0; kk < 16; kk++) {
            float4 a = *reinterpret_cast<float4*>(&As[kk][ty * 4]);
            float4 b = *reinterpret_cast<float4*>(&Bs[kk][tx * 4]);
            acc[0][0] = fmaf(a.x, b.x, acc[0][0]); acc[0][1] = fmaf(a.x, b.y, acc[0][1]);
            acc[0][2] = fmaf(a.x, b.z, acc[0][2]); acc[0][3] = fmaf(a.x, b.w, acc[0][3]);
            acc[1][0] = fmaf(a.y, b.x, acc[1][0]); acc[1][1] = fmaf(a.y, b.y, acc[1][1]);
            acc[1][2] = fmaf(a.y, b.z, acc[1][2]); acc[1][3] = fmaf(a.y, b.w, acc[1][3]);
            acc[2][0] = fmaf(a.z, b.x, acc[2][0]); acc[2][1] = fmaf(a.z, b.y, acc[2][1]);
            acc[2][2] = fmaf(a.z, b.z, acc[2][2]); acc[2][3] = fmaf(a.z, b.w, acc[2][3]);
            acc[3][0] = fmaf(a.w, b.x, acc[3][0]); acc[3][1] = fmaf(a.w, b.y, acc[3][1]);
            acc[3][2] = fmaf(a.w, b.z, acc[3][2]); acc[3][3] = fmaf(a.w, b.w, acc[3][3]);
        }
        __syncthreads();
    }
    #pragma unroll
    for (int i = 0; i < 4; i++) {
        const int m = m0 + ty * 4 + i;
        #pragma unroll
        for (int j = 0; j < 4; j++) {
            const int n = n0 + tx * 4 + j;
            if (n < N) {
                float v = acc[i][j] + bias[n];
                if (RELU) v = fmaxf(v, 0.f);
                C[(size_t)m * ldc + coff + n] = v;
            }
        }
    }
}

// ============================== Launch ==============================
extern "C" void kernel_launch(void* const* d_in, const int* in_sizes, int n_in,
                              void* d_out, int out_size)
{
    const float* tot_obj_pts = (const float*)d_in[0];
    const float* src_feat    = (const float*)d_in[1];
    const float* ref_feat    = (const float*)d_in[2];
    const float* sg_w1 = (const float*)d_in[6];
    const float* sg_b1 = (const float*)d_in[7];
    const float* sg_w2 = (const float*)d_in[8];
    const float* sg_b2 = (const float*)d_in[9];
    const float* se_w  = (const float*)d_in[10];
    const float* se_b  = (const float*)d_in[11];
    const float* p_w1  = (const float*)d_in[12];
    const float* p_b1  = (const float*)d_in[13];
    const float* p_w2  = (const float*)d_in[14];
    const float* p_b2  = (const float*)d_in[15];
    const float* p_w3  = (const float*)d_in[16];
    const float* p_b3  = (const float*)d_in[17];
    const float* oe_w  = (const float*)d_in[18];
    const float* oe_b  = (const float*)d_in[19];
    float* out = (float*)d_out;

    void *py1, *py2, *pfeat;
    cudaGetSymbolAddress(&py1, g_y1);
    cudaGetSymbolAddress(&py2, g_y2);
    cudaGetSymbolAddress(&pfeat, g_feat);
    float* y1 = (float*)py1;
    float* y2 = (float*)py2;
    float* feat = (float*)pfeat;

    int sms = 148;
    cudaDeviceGetAttribute(&sms, cudaDevAttrMultiProcessorCount, 0);

    cudaFuncSetAttribute(pointnet_mma,
                         cudaFuncAttributeMaxDynamicSharedMemorySize, SM_TOTAL);

    // PointNet branch on tensor cores (mma.sync f16), persistent grid
    pointnet_mma<<<sms, 512, SM_TOTAL>>>(
        tot_obj_pts, p_w1, p_b1, p_w2, p_b2, p_w3, p_b3, feat, NTOT);

    // sgnet chain (gather fused into stage 1)
    {
        dim3 grid(256 / 64, NTOT / 64);
        gemm64_kernel<true, true><<<grid, 256>>>(
            nullptr, src_feat, ref_feat, sg_w1, sg_b1, y1, NTOT, 256, 256, 256, 0);
        gemm64_kernel<false, false><<<grid, 256>>>(
            y1, nullptr, nullptr, sg_w2, sg_b2, y2, NTOT, 256, 256, 256, 0);
    }
    {
        dim3 grid((EMB + 63) / 64, NTOT / 64);
        gemm64_kernel<false, false><<<grid, 256>>>(
            y2, nullptr, nullptr, se_w, se_b, out, NTOT, EMB, 256, 200, 0);
        gemm64_kernel<false, false><<<grid, 256>>>(
            feat, nullptr, nullptr, oe_w, oe_b, out, NTOT, EMB, 256, 200, 100);
    }
}

// round 6
// speedup vs baseline: 5.9808x; 1.2476x over previous
#include <cuda_runtime.h>
#include <cuda_fp16.h>
#include <cstdint>

#define NTOT 16384
#define EMB  100

// Scratch (device globals — no runtime allocation allowed).
__device__ __half g_h1[NTOT * 256];   // relu(gather@sg_w1+b1), f16
__device__ __half g_h2[NTOT * 256];   // h1@sg_w2+b2, f16
__device__ float  g_feat[NTOT * 256]; // pointnet pooled features, f32

// ============================== helpers ==============================
__device__ __forceinline__ uint32_t smem_u32(const void* p) {
    uint32_t a;
    asm("{ .reg .u64 t; cvta.to.shared.u64 t, %1; cvt.u32.u64 %0, t; }"
        : "=r"(a) : "l"(p));
    return a;
}
__device__ __forceinline__ uint32_t pack2(float lo, float hi) {
    __half2 h = __floats2half2_rn(lo, hi);
    return *reinterpret_cast<uint32_t*>(&h);
}
__device__ __forceinline__ void ldsm_x4(uint32_t& r0, uint32_t& r1, uint32_t& r2, uint32_t& r3,
                                        uint32_t addr) {
    asm volatile("ldmatrix.sync.aligned.m8n8.x4.shared.b16 {%0,%1,%2,%3}, [%4];"
                 : "=r"(r0), "=r"(r1), "=r"(r2), "=r"(r3) : "r"(addr));
}
__device__ __forceinline__ void ldsm_x2t(uint32_t& r0, uint32_t& r1, uint32_t addr) {
    asm volatile("ldmatrix.sync.aligned.m8n8.x2.trans.shared.b16 {%0,%1}, [%2];"
                 : "=r"(r0), "=r"(r1) : "r"(addr));
}
__device__ __forceinline__ void mma16816(float* c, const uint32_t* a, uint32_t b0, uint32_t b1) {
    asm volatile("mma.sync.aligned.m16n8k16.row.col.f32.f16.f16.f32 "
                 "{%0,%1,%2,%3}, {%4,%5,%6,%7}, {%8,%9}, {%0,%1,%2,%3};"
                 : "+f"(c[0]), "+f"(c[1]), "+f"(c[2]), "+f"(c[3])
                 : "r"(a[0]), "r"(a[1]), "r"(a[2]), "r"(a[3]), "r"(b0), "r"(b1));
}

// ============================== PointNet (mma.sync f16) ==============================
// SMEM byte offsets
#define SM_W3   0        /* 128 x 512B  (f16, swizzled)  = 65536 */
#define SM_W2   65536    /* 64  x 256B                    = 16384 */
#define SM_H2   81920    /* 128 x 256B                    = 32768 */
#define SM_H1   114688   /* 128 x 128B                    = 16384 */
#define SM_PART 131072   /* 4 x 256 f32                   = 4096  */
#define SM_B2   135168   /* 128 f32 */
#define SM_B3   135680   /* 256 f32 */
#define SM_W1   136704   /* 192 f32 */
#define SM_B1   137472   /* 64  f32 */
#define SM_TOTAL 137728

__global__ __launch_bounds__(512, 1) void pointnet_mma(
    const float* __restrict__ pts,
    const float* __restrict__ w1, const float* __restrict__ b1,
    const float* __restrict__ w2, const float* __restrict__ b2,
    const float* __restrict__ w3, const float* __restrict__ b3,
    float* __restrict__ feat_out, int ntot)
{
    extern __shared__ char sm[];
    const uint32_t s0 = smem_u32(sm);
    const int tid = threadIdx.x;
    const int wid = tid >> 5, lane = tid & 31;

    // ---- Stage weights (once per block) ----
    for (int i = tid * 8; i < 128 * 256; i += 512 * 8) {
        int k = i >> 8, n = i & 255;
        float4 f0 = *reinterpret_cast<const float4*>(w3 + i);
        float4 f1 = *reinterpret_cast<const float4*>(w3 + i + 4);
        uint4 u = make_uint4(pack2(f0.x, f0.y), pack2(f0.z, f0.w),
                             pack2(f1.x, f1.y), pack2(f1.z, f1.w));
        int ch = (n >> 3) ^ (k & 7);
        *reinterpret_cast<uint4*>(sm + SM_W3 + k * 512 + ch * 16) = u;
    }
    for (int i = tid * 8; i < 64 * 128; i += 512 * 8) {
        int k = i >> 7, n = i & 127;
        float4 f0 = *reinterpret_cast<const float4*>(w2 + i);
        float4 f1 = *reinterpret_cast<const float4*>(w2 + i + 4);
        uint4 u = make_uint4(pack2(f0.x, f0.y), pack2(f0.z, f0.w),
                             pack2(f1.x, f1.y), pack2(f1.z, f1.w));
        int ch = (n >> 3) ^ (k & 7);
        *reinterpret_cast<uint4*>(sm + SM_W2 + k * 256 + ch * 16) = u;
    }
    if (tid < 128) reinterpret_cast<float*>(sm + SM_B2)[tid] = b2[tid];
    if (tid < 256) reinterpret_cast<float*>(sm + SM_B3)[tid] = b3[tid];
    if (tid < 192) reinterpret_cast<float*>(sm + SM_W1)[tid] = w1[tid];
    if (tid < 64)  reinterpret_cast<float*>(sm + SM_B1)[tid] = b1[tid];
    __syncthreads();

    const float* sW1f = reinterpret_cast<const float*>(sm + SM_W1);
    const float* sB1f = reinterpret_cast<const float*>(sm + SM_B1);
    const float* sB2f = reinterpret_cast<const float*>(sm + SM_B2);
    const float* sB3f = reinterpret_cast<const float*>(sm + SM_B3);
    float* sPart = reinterpret_cast<float*>(sm + SM_PART);

    const int g = lane >> 2, tig = lane & 3;
    const int rt = wid >> 2, ct = wid & 3;
    const int r0 = rt * 32;
    const int row = tid >> 2, q = tid & 3;

    // Prefetch first object's coords
    float nx0 = 0.f, nx1 = 0.f, nx2 = 0.f;
    if (blockIdx.x < (unsigned)ntot) {
        const float* pr = pts + (size_t)blockIdx.x * 384 + row * 3;
        nx0 = pr[0]; nx1 = pr[1]; nx2 = pr[2];
    }

    for (int obj = blockIdx.x; obj < ntot; obj += gridDim.x) {
        // ---- H1 = relu(pts@W1 + b1) -> sH1 (f16, swizzled) ----
        {
            const float x0 = nx0, x1 = nx1, x2 = nx2;
            uint32_t u[8];
            #pragma unroll
            for (int e = 0; e < 8; e++) {
                const int c0 = q * 16 + e * 2;
                float v0 = fmaf(x2, sW1f[128 + c0],
                           fmaf(x1, sW1f[64 + c0], fmaf(x0, sW1f[c0], sB1f[c0])));
                float v1 = fmaf(x2, sW1f[129 + c0],
                           fmaf(x1, sW1f[65 + c0], fmaf(x0, sW1f[c0 + 1], sB1f[c0 + 1])));
                u[e] = pack2(fmaxf(v0, 0.f), fmaxf(v1, 0.f));
            }
            const int ch0 = (q * 2) ^ (row & 7), ch1 = (q * 2 + 1) ^ (row & 7);
            *reinterpret_cast<uint4*>(sm + SM_H1 + row * 128 + ch0 * 16) =
                make_uint4(u[0], u[1], u[2], u[3]);
            *reinterpret_cast<uint4*>(sm + SM_H1 + row * 128 + ch1 * 16) =
                make_uint4(u[4], u[5], u[6], u[7]);
            // Prefetch next object's coords (latency hidden under phase1+phase2)
            const int nobj = obj + gridDim.x;
            if (nobj < ntot) {
                const float* pr = pts + (size_t)nobj * 384 + row * 3;
                nx0 = pr[0]; nx1 = pr[1]; nx2 = pr[2];
            }
        }
        __syncthreads();

        // ---- Phase 1: H2 = relu(H1 @ W2 + b2), warp tile 32x32 ----
        {
            const int n0 = ct * 32;
            uint32_t a[2][4][4];
            #pragma unroll
            for (int rg = 0; rg < 2; rg++)
                #pragma unroll
                for (int kb = 0; kb < 4; kb++) {
                    const int rr = r0 + rg * 16 + (lane & 15);
                    const int ch = (kb * 2 + (lane >> 4)) ^ (rr & 7);
                    ldsm_x4(a[rg][kb][0], a[rg][kb][1], a[rg][kb][2], a[rg][kb][3],
                            s0 + SM_H1 + rr * 128 + ch * 16);
                }
            float c[2][4][4] = {};
            #pragma unroll
            for (int nb = 0; nb < 4; nb++) {
                const int nch = (n0 >> 3) + nb;
                #pragma unroll
                for (int kb = 0; kb < 4; kb++) {
                    const int krow = kb * 16 + (lane & 15);
                    uint32_t b0, b1;
                    ldsm_x2t(b0, b1, s0 + SM_W2 + krow * 256 + ((nch ^ (krow & 7)) * 16));
                    mma16816(c[0][nb], a[0][kb], b0, b1);
                    mma16816(c[1][nb], a[1][kb], b0, b1);
                }
            }
            #pragma unroll
            for (int rg = 0; rg < 2; rg++) {
                const int rowa = r0 + rg * 16 + g, rowb = rowa + 8;
                #pragma unroll
                for (int nb = 0; nb < 4; nb++) {
                    const int col = n0 + nb * 8 + 2 * tig;
                    const float bb0 = sB2f[col], bb1 = sB2f[col + 1];
                    const uint32_t p0 = pack2(fmaxf(c[rg][nb][0] + bb0, 0.f),
                                              fmaxf(c[rg][nb][1] + bb1, 0.f));
                    const uint32_t p1 = pack2(fmaxf(c[rg][nb][2] + bb0, 0.f),
                                              fmaxf(c[rg][nb][3] + bb1, 0.f));
                    const int nch = (n0 >> 3) + nb;
                    *reinterpret_cast<uint32_t*>(
                        sm + SM_H2 + rowa * 256 + ((nch ^ (rowa & 7)) * 16) + tig * 4) = p0;
                    *reinterpret_cast<uint32_t*>(
                        sm + SM_H2 + rowb * 256 + ((nch ^ (rowb & 7)) * 16) + tig * 4) = p1;
                }
            }
        }
        __syncthreads();

        // ---- Phase 2: H3 = H2 @ W3, fused column-max ----
        {
            uint32_t a[2][8][4];
            #pragma unroll
            for (int rg = 0; rg < 2; rg++)
                #pragma unroll
                for (int kb = 0; kb < 8; kb++) {
                    const int rr = r0 + rg * 16 + (lane & 15);
                    const int ch = (kb * 2 + (lane >> 4)) ^ (rr & 7);
                    ldsm_x4(a[rg][kb][0], a[rg][kb][1], a[rg][kb][2], a[rg][kb][3],
                            s0 + SM_H2 + rr * 256 + ch * 16);
                }
            #pragma unroll
            for (int tile = 0; tile < 2; tile++) {
                const int n0 = ct * 32 + tile * 128;
                float c[2][4][4] = {};
                #pragma unroll
                for (int nb = 0; nb < 4; nb++) {
                    const int nch = (n0 >> 3) + nb;
                    #pragma unroll
                    for (int kb = 0; kb < 8; kb++) {
                        const int krow = kb * 16 + (lane & 15);
                        uint32_t b0, b1;
                        ldsm_x2t(b0, b1, s0 + SM_W3 + krow * 512 + ((nch ^ (krow & 7)) * 16));
                        mma16816(c[0][nb], a[0][kb], b0, b1);
                        mma16816(c[1][nb], a[1][kb], b0, b1);
                    }
                }
                #pragma unroll
                for (int nb = 0; nb < 4; nb++) {
                    float m0 = fmaxf(fmaxf(c[0][nb][0], c[0][nb][2]),
                                     fmaxf(c[1][nb][0], c[1][nb][2]));
                    float m1 = fmaxf(fmaxf(c[0][nb][1], c[0][nb][3]),
                                     fmaxf(c[1][nb][1], c[1][nb][3]));
                    #pragma unroll
                    for (int off = 4; off < 32; off <<= 1) {
                        m0 = fmaxf(m0, __shfl_xor_sync(0xffffffff, m0, off));
                        m1 = fmaxf(m1, __shfl_xor_sync(0xffffffff, m1, off));
                    }
                    if (lane < 4) {
                        sPart[rt * 256 + n0 + nb * 8 + 2 * tig]     = m0;
                        sPart[rt * 256 + n0 + nb * 8 + 2 * tig + 1] = m1;
                    }
                }
            }
        }
        __syncthreads();

        if (tid < 256) {
            const float v = fmaxf(fmaxf(sPart[tid], sPart[256 + tid]),
                                  fmaxf(sPart[512 + tid], sPart[768 + tid]));
            feat_out[(size_t)obj * 256 + tid] = v + sB3f[tid];
        }
        // no trailing barrier: next write targets (SM_H1) are disjoint from
        // sPart reads above, and all earlier readers are behind 2 barriers.
    }
}

// ============================== sgnet mma GEMM (128-row tiles) ==============================
// C[blk*128 + m, n] = (relu?)(A @ W + bias); A gathered / f32 / f16.
// NPAD: padded N in smem (256 or 128). nmax: true N.
// Warp tile: 32 rows x (NPAD/4) cols -> NJ = NPAD/32 chunks of 8 columns.
template <bool GATHER, bool RELU, bool IN_F16, bool OUT_F16, int NPAD>
__global__ __launch_bounds__(512) void mma_gemm(
    const void* __restrict__ Ain,
    const float* __restrict__ Asrc, const float* __restrict__ Aref,
    const float* __restrict__ W, const float* __restrict__ bias,
    void* __restrict__ Cout, int nmax, int ldc, int coff)
{
    extern __shared__ char sm[];
    const uint32_t s0 = smem_u32(sm);
    char* sA = sm;                         // 128 x 512B
    char* sW = sm + 65536;                 // 256 x (NPAD*2)B
    float* sBias = reinterpret_cast<float*>(sW + 256 * NPAD * 2);

    const int tid = threadIdx.x;
    const int wid = tid >> 5, lane = tid & 31;
    const int m0 = blockIdx.x * 128;

    // ---- Stage A tile (f16, swizzled; rowBytes = 512) ----
    {
        const int r = tid >> 2, q = tid & 3;
        const int m = m0 + r;
        if (IN_F16) {
            const __half* arow = reinterpret_cast<const __half*>(Ain) + (size_t)m * 256;
            #pragma unroll
            for (int e = 0; e < 8; e++) {
                const int c = q * 8 + e;
                uint4 u = *reinterpret_cast<const uint4*>(arow + c * 8);
                *reinterpret_cast<uint4*>(sA + r * 512 + ((c ^ (r & 7)) * 16)) = u;
            }
        } else {
            const float* arow;
            if (GATHER) {
                const int b = m >> 10, j = m & 1023;
                arow = (j < 512) ? (Asrc + (size_t)(b * 512 + j) * 256)
                                 : (Aref + (size_t)(b * 512 + (j - 512)) * 256);
            } else {
                arow = reinterpret_cast<const float*>(Ain) + (size_t)m * 256;
            }
            #pragma unroll
            for (int e = 0; e < 8; e++) {
                const int c = q * 8 + e;
                float4 f0 = *reinterpret_cast<const float4*>(arow + c * 8);
                float4 f1 = *reinterpret_cast<const float4*>(arow + c * 8 + 4);
                uint4 u = make_uint4(pack2(f0.x, f0.y), pack2(f0.z, f0.w),
                                     pack2(f1.x, f1.y), pack2(f1.z, f1.w));
                *reinterpret_cast<uint4*>(sA + r * 512 + ((c ^ (r & 7)) * 16)) = u;
            }
        }
    }
    // ---- Stage W (256 x NPAD f16, swizzled) ----
    {
        const int r = tid >> 1, h = tid & 1;
        const int CH = NPAD / 16;       // 16B chunks per half-row job (row = NPAD/8 chunks)
        #pragma unroll
        for (int e = 0; e < CH; e++) {
            const int c = h * CH + e;
            uint4 u;
            if (NPAD == 256) {
                float4 f0 = *reinterpret_cast<const float4*>(W + (size_t)r * nmax + c * 8);
                float4 f1 = *reinterpret_cast<const float4*>(W + (size_t)r * nmax + c * 8 + 4);
                u = make_uint4(pack2(f0.x, f0.y), pack2(f0.z, f0.w),
                               pack2(f1.x, f1.y), pack2(f1.z, f1.w));
            } else {
                float v[8];
                #pragma unroll
                for (int i = 0; i < 8; i++) {
                    const int col = c * 8 + i;
                    v[i] = (col < nmax) ? W[(size_t)r * nmax + col] : 0.f;
                }
                u = make_uint4(pack2(v[0], v[1]), pack2(v[2], v[3]),
                               pack2(v[4], v[5]), pack2(v[6], v[7]));
            }
            *reinterpret_cast<uint4*>(sW + r * (NPAD * 2) + ((c ^ (r & 7)) * 16)) = u;
        }
    }
    if (tid < NPAD) sBias[tid] = (tid < nmax) ? bias[tid] : 0.f;
    __syncthreads();

    // ---- Compute: warp (rt, ct); warp tile 32 x (NPAD/4) ----
    const int g = lane >> 2, tig = lane & 3;
    const int rt = wid >> 2, ct = wid & 3;
    const int r0 = rt * 32;
    const int NJ = NPAD / 32;           // 8-col chunks per warp
    const int n0 = ct * (NPAD / 4);

    float c[2][NPAD / 32][4];
    #pragma unroll
    for (int rg = 0; rg < 2; rg++)
        #pragma unroll
        for (int j = 0; j < NJ; j++)
            #pragma unroll
            for (int e = 0; e < 4; e++) c[rg][j][e] = 0.f;

    const uint32_t wRowB = NPAD * 2;
    #pragma unroll
    for (int kb = 0; kb < 16; kb++) {
        uint32_t a[2][4];
        #pragma unroll
        for (int rg = 0; rg < 2; rg++) {
            const int rr = r0 + rg * 16 + (lane & 15);
            const int ch = (kb * 2 + (lane >> 4)) ^ (rr & 7);
            ldsm_x4(a[rg][0], a[rg][1], a[rg][2], a[rg][3],
                    s0 + rr * 512 + ch * 16);
        }
        const int krow = kb * 16 + (lane & 15);
        #pragma unroll
        for (int j = 0; j < NJ; j++) {
            const int nch = (n0 >> 3) + j;
            uint32_t b0, b1;
            ldsm_x2t(b0, b1, s0 + 65536 + krow * wRowB + ((nch ^ (krow & 7)) * 16));
            mma16816(c[0][j], a[0], b0, b1);
            mma16816(c[1][j], a[1], b0, b1);
        }
    }

    // ---- Epilogue ----
    #pragma unroll
    for (int rg = 0; rg < 2; rg++) {
        const int rowa = m0 + r0 + rg * 16 + g;
        #pragma unroll
        for (int j = 0; j < NJ; j++) {
            const int col = n0 + j * 8 + 2 * tig;
            float v0 = c[rg][j][0] + sBias[col];
            float v1 = c[rg][j][1] + sBias[col + 1];
            float v2 = c[rg][j][2] + sBias[col];
            float v3 = c[rg][j][3] + sBias[col + 1];
            if (RELU) {
                v0 = fmaxf(v0, 0.f); v1 = fmaxf(v1, 0.f);
                v2 = fmaxf(v2, 0.f); v3 = fmaxf(v3, 0.f);
            }
            if (OUT_F16) {
                __half* y = reinterpret_cast<__half*>(Cout);
                *reinterpret_cast<uint32_t*>(y + (size_t)rowa * 256 + col) = pack2(v0, v1);
                *reinterpret_cast<uint32_t*>(y + (size_t)(rowa + 8) * 256 + col) = pack2(v2, v3);
            } else {
                float* o = reinterpret_cast<float*>(Cout);
                if (col < nmax) {
                    o[(size_t)rowa * ldc + coff + col] = v0;
                    o[(size_t)(rowa + 8) * ldc + coff + col] = v2;
                }
                if (col + 1 < nmax) {
                    o[(size_t)rowa * ldc + coff + col + 1] = v1;
                    o[(size_t)(rowa + 8) * ldc + coff + col + 1] = v3;
                }
            }
        }
    }
}

// ============================== Launch ==============================
extern "C" void kernel_launch(void* const* d_in, const int* in_sizes, int n_in,
                              void* d_out, int out_size)
{
    const float* tot_obj_pts = (const float*)d_in[0];
    const float* src_feat    = (const float*)d_in[1];
    const float* ref_feat    = (const float*)d_in[2];
    const float* sg_w1 = (const float*)d_in[6];
    const float* sg_b1 = (const float*)d_in[7];
    const float* sg_w2 = (const float*)d_in[8];
    const float* sg_b2 = (const float*)d_in[9];
    const float* se_w  = (const float*)d_in[10];
    const float* se_b  = (const float*)d_in[11];
    const float* p_w1  = (const float*)d_in[12];
    const float* p_b1  = (const float*)d_in[13];
    const float* p_w2  = (const float*)d_in[14];
    const float* p_b2  = (const float*)d_in[15];
    const float* p_w3  = (const float*)d_in[16];
    const float* p_b3  = (const float*)d_in[17];
    const float* oe_w  = (const float*)d_in[18];
    const float* oe_b  = (const float*)d_in[19];
    float* out = (float*)d_out;

    void *ph1, *ph2, *pfeat;
    cudaGetSymbolAddress(&ph1, g_h1);
    cudaGetSymbolAddress(&ph2, g_h2);
    cudaGetSymbolAddress(&pfeat, g_feat);

    int sms = 148;
    cudaDeviceGetAttribute(&sms, cudaDevAttrMultiProcessorCount, 0);

    cudaFuncSetAttribute(pointnet_mma,
                         cudaFuncAttributeMaxDynamicSharedMemorySize, SM_TOTAL);

    // PointNet branch (dominant)
    pointnet_mma<<<sms, 512, SM_TOTAL>>>(
        tot_obj_pts, p_w1, p_b1, p_w2, p_b2, p_w3, p_b3, (float*)pfeat, NTOT);

    // sgnet chain on tensor cores
    const int SMEM_256 = 65536 + 131072 + 1024;   // 197632
    const int SMEM_128 = 65536 + 65536 + 512;     // 131584

    auto k1 = mma_gemm<true,  true,  false, true, 256>;
    auto k2 = mma_gemm<false, false, true,  true, 256>;
    auto k3 = mma_gemm<false, false, true,  false, 128>;
    auto k4 = mma_gemm<false, false, false, false, 128>;
    cudaFuncSetAttribute(k1, cudaFuncAttributeMaxDynamicSharedMemorySize, SMEM_256);
    cudaFuncSetAttribute(k2, cudaFuncAttributeMaxDynamicSharedMemorySize, SMEM_256);
    cudaFuncSetAttribute(k3, cudaFuncAttributeMaxDynamicSharedMemorySize, SMEM_128);
    cudaFuncSetAttribute(k4, cudaFuncAttributeMaxDynamicSharedMemorySize, SMEM_128);

    // h1 = relu(gather(src,ref) @ sg_w1 + sg_b1)
    k1<<<NTOT / 128, 512, SMEM_256>>>(nullptr, src_feat, ref_feat,
                                      sg_w1, sg_b1, ph1, 256, 0, 0);
    // h2 = h1 @ sg_w2 + sg_b2
    k2<<<NTOT / 128, 512, SMEM_256>>>(ph1, nullptr, nullptr,
                                      sg_w2, sg_b2, ph2, 256, 0, 0);
    // out[:, 0:100] = h2 @ se_w + se_b
    k3<<<NTOT / 128, 512, SMEM_128>>>(ph2, nullptr, nullptr,
                                      se_w, se_b, out, EMB, 200, 0);
    // out[:, 100:200] = feat @ oe_w + oe_b
    k4<<<NTOT / 128, 512, SMEM_128>>>(pfeat, nullptr, nullptr,
                                      oe_w, oe_b, out, EMB, 200, 100);
}

// round 7
// speedup vs baseline: 6.1753x; 1.0325x over previous
#include <cuda_runtime.h>
#include <cuda_fp16.h>
#include <cstdint>

#define NTOT 16384
#define EMB  100

// Scratch (device globals — no runtime allocation allowed).
__device__ __half g_h1[NTOT * 256];   // relu(gather@sg_w1+b1), f16
__device__ __half g_h2[NTOT * 256];   // h1@sg_w2+b2, f16
__device__ float  g_feat[NTOT * 256]; // pointnet pooled features, f32

// ============================== helpers ==============================
__device__ __forceinline__ uint32_t smem_u32(const void* p) {
    uint32_t a;
    asm("{ .reg .u64 t; cvta.to.shared.u64 t, %1; cvt.u32.u64 %0, t; }"
        : "=r"(a) : "l"(p));
    return a;
}
__device__ __forceinline__ uint32_t pack2(float lo, float hi) {
    __half2 h = __floats2half2_rn(lo, hi);
    return *reinterpret_cast<uint32_t*>(&h);
}
__device__ __forceinline__ void ldsm_x4(uint32_t& r0, uint32_t& r1, uint32_t& r2, uint32_t& r3,
                                        uint32_t addr) {
    asm volatile("ldmatrix.sync.aligned.m8n8.x4.shared.b16 {%0,%1,%2,%3}, [%4];"
                 : "=r"(r0), "=r"(r1), "=r"(r2), "=r"(r3) : "r"(addr));
}
__device__ __forceinline__ void ldsm_x2t(uint32_t& r0, uint32_t& r1, uint32_t addr) {
    asm volatile("ldmatrix.sync.aligned.m8n8.x2.trans.shared.b16 {%0,%1}, [%2];"
                 : "=r"(r0), "=r"(r1) : "r"(addr));
}
__device__ __forceinline__ void ldsm_x4t(uint32_t& r0, uint32_t& r1, uint32_t& r2, uint32_t& r3,
                                         uint32_t addr) {
    asm volatile("ldmatrix.sync.aligned.m8n8.x4.trans.shared.b16 {%0,%1,%2,%3}, [%4];"
                 : "=r"(r0), "=r"(r1), "=r"(r2), "=r"(r3) : "r"(addr));
}
__device__ __forceinline__ void mma16816(float* c, const uint32_t* a, uint32_t b0, uint32_t b1) {
    asm volatile("mma.sync.aligned.m16n8k16.row.col.f32.f16.f16.f32 "
                 "{%0,%1,%2,%3}, {%4,%5,%6,%7}, {%8,%9}, {%0,%1,%2,%3};"
                 : "+f"(c[0]), "+f"(c[1]), "+f"(c[2]), "+f"(c[3])
                 : "r"(a[0]), "r"(a[1]), "r"(a[2]), "r"(a[3]), "r"(b0), "r"(b1));
}
#define NAMED_BAR(id) \
    asm volatile("bar.sync %0, 128;" :: "r"(id) : "memory")

// ============================== PointNet (mma.sync f16) ==============================
// SMEM byte offsets
#define SM_W3   0        /* 128 x 512B  (f16, swizzled)  = 65536 */
#define SM_W2   65536    /* 64  x 256B                    = 16384 */
#define SM_H2   81920    /* 128 x 256B                    = 32768 */
#define SM_H1   114688   /* 128 x 128B                    = 16384 */
#define SM_PART 131072   /* 2 x 4 x 256 f32 (dbl-buf)     = 8192  */
#define SM_B2   139264   /* 128 f32 */
#define SM_B3   139776   /* 256 f32 */
#define SM_W1   140800   /* 192 f32 */
#define SM_B1   141568   /* 64  f32 */
#define SM_TOTAL 141824

__global__ __launch_bounds__(512, 1) void pointnet_mma(
    const float* __restrict__ pts,
    const float* __restrict__ w1, const float* __restrict__ b1,
    const float* __restrict__ w2, const float* __restrict__ b2,
    const float* __restrict__ w3, const float* __restrict__ b3,
    float* __restrict__ feat_out, int ntot)
{
    extern __shared__ char sm[];
    const uint32_t s0 = smem_u32(sm);
    const int tid = threadIdx.x;
    const int wid = tid >> 5, lane = tid & 31;

    // ---- Stage weights (once per block) ----
    for (int i = tid * 8; i < 128 * 256; i += 512 * 8) {
        int k = i >> 8, n = i & 255;
        float4 f0 = *reinterpret_cast<const float4*>(w3 + i);
        float4 f1 = *reinterpret_cast<const float4*>(w3 + i + 4);
        uint4 u = make_uint4(pack2(f0.x, f0.y), pack2(f0.z, f0.w),
                             pack2(f1.x, f1.y), pack2(f1.z, f1.w));
        int ch = (n >> 3) ^ (k & 7);
        *reinterpret_cast<uint4*>(sm + SM_W3 + k * 512 + ch * 16) = u;
    }
    for (int i = tid * 8; i < 64 * 128; i += 512 * 8) {
        int k = i >> 7, n = i & 127;
        float4 f0 = *reinterpret_cast<const float4*>(w2 + i);
        float4 f1 = *reinterpret_cast<const float4*>(w2 + i + 4);
        uint4 u = make_uint4(pack2(f0.x, f0.y), pack2(f0.z, f0.w),
                             pack2(f1.x, f1.y), pack2(f1.z, f1.w));
        int ch = (n >> 3) ^ (k & 7);
        *reinterpret_cast<uint4*>(sm + SM_W2 + k * 256 + ch * 16) = u;
    }
    if (tid < 128) reinterpret_cast<float*>(sm + SM_B2)[tid] = b2[tid];
    if (tid < 256) reinterpret_cast<float*>(sm + SM_B3)[tid] = b3[tid];
    if (tid < 192) reinterpret_cast<float*>(sm + SM_W1)[tid] = w1[tid];
    if (tid < 64)  reinterpret_cast<float*>(sm + SM_B1)[tid] = b1[tid];
    __syncthreads();

    const float* sW1f = reinterpret_cast<const float*>(sm + SM_W1);
    const float* sB1f = reinterpret_cast<const float*>(sm + SM_B1);
    const float* sB2f = reinterpret_cast<const float*>(sm + SM_B2);
    const float* sB3f = reinterpret_cast<const float*>(sm + SM_B3);

    const int g = lane >> 2, tig = lane & 3;
    const int rt = wid >> 2, ct = wid & 3;
    const int r0 = rt * 32;
    const int row = tid >> 2, q = tid & 3;
    const int barid = 1 + rt;           // named barrier per 4-warp group
    const int qh = lane >> 3;           // quad for x4t addressing
    const int ql = lane & 7;

    // Prefetch first object's coords
    float nx0 = 0.f, nx1 = 0.f, nx2 = 0.f;
    if (blockIdx.x < (unsigned)ntot) {
        const float* pr = pts + (size_t)blockIdx.x * 384 + row * 3;
        nx0 = pr[0]; nx1 = pr[1]; nx2 = pr[2];
    }

    int pb = 0;   // sPart buffer parity

    for (int obj = blockIdx.x; obj < ntot; obj += gridDim.x) {
        float* sPart = reinterpret_cast<float*>(sm + SM_PART) + pb * 1024;

        // ---- H1 = relu(pts@W1 + b1) -> sH1 (f16, swizzled) ----
        {
            const float x0 = nx0, x1 = nx1, x2 = nx2;
            uint32_t u[8];
            #pragma unroll
            for (int e = 0; e < 8; e++) {
                const int c0 = q * 16 + e * 2;
                float v0 = fmaf(x2, sW1f[128 + c0],
                           fmaf(x1, sW1f[64 + c0], fmaf(x0, sW1f[c0], sB1f[c0])));
                float v1 = fmaf(x2, sW1f[129 + c0],
                           fmaf(x1, sW1f[65 + c0], fmaf(x0, sW1f[c0 + 1], sB1f[c0 + 1])));
                u[e] = pack2(fmaxf(v0, 0.f), fmaxf(v1, 0.f));
            }
            const int ch0 = (q * 2) ^ (row & 7), ch1 = (q * 2 + 1) ^ (row & 7);
            *reinterpret_cast<uint4*>(sm + SM_H1 + row * 128 + ch0 * 16) =
                make_uint4(u[0], u[1], u[2], u[3]);
            *reinterpret_cast<uint4*>(sm + SM_H1 + row * 128 + ch1 * 16) =
                make_uint4(u[4], u[5], u[6], u[7]);
            // Prefetch next object's coords
            const int nobj = obj + gridDim.x;
            if (nobj < ntot) {
                const float* pr = pts + (size_t)nobj * 384 + row * 3;
                nx0 = pr[0]; nx1 = pr[1]; nx2 = pr[2];
            }
        }
        NAMED_BAR(barid);   // H1 rows of this group ready for this group

        // ---- Phase 1: H2 = relu(H1 @ W2 + b2), warp tile 32x32 ----
        {
            const int n0 = ct * 32;
            uint32_t a[2][4][4];
            #pragma unroll
            for (int rg = 0; rg < 2; rg++)
                #pragma unroll
                for (int kb = 0; kb < 4; kb++) {
                    const int rr = r0 + rg * 16 + (lane & 15);
                    const int ch = (kb * 2 + (lane >> 4)) ^ (rr & 7);
                    ldsm_x4(a[rg][kb][0], a[rg][kb][1], a[rg][kb][2], a[rg][kb][3],
                            s0 + SM_H1 + rr * 128 + ch * 16);
                }
            float c[2][4][4] = {};
            #pragma unroll
            for (int kb = 0; kb < 4; kb++) {
                const int krow = kb * 16 + (qh & 1) * 8 + ql;
                #pragma unroll
                for (int jp = 0; jp < 2; jp++) {
                    const int nch = (n0 >> 3) + jp * 2 + (qh >> 1);
                    uint32_t b0, b1, b2r, b3r;
                    ldsm_x4t(b0, b1, b2r, b3r,
                             s0 + SM_W2 + krow * 256 + ((nch ^ (krow & 7)) * 16));
                    mma16816(c[0][jp * 2],     a[0][kb], b0, b1);
                    mma16816(c[1][jp * 2],     a[1][kb], b0, b1);
                    mma16816(c[0][jp * 2 + 1], a[0][kb], b2r, b3r);
                    mma16816(c[1][jp * 2 + 1], a[1][kb], b2r, b3r);
                }
            }
            #pragma unroll
            for (int rg = 0; rg < 2; rg++) {
                const int rowa = r0 + rg * 16 + g, rowb = rowa + 8;
                #pragma unroll
                for (int nb = 0; nb < 4; nb++) {
                    const int col = n0 + nb * 8 + 2 * tig;
                    const float bb0 = sB2f[col], bb1 = sB2f[col + 1];
                    const uint32_t p0 = pack2(fmaxf(c[rg][nb][0] + bb0, 0.f),
                                              fmaxf(c[rg][nb][1] + bb1, 0.f));
                    const uint32_t p1 = pack2(fmaxf(c[rg][nb][2] + bb0, 0.f),
                                              fmaxf(c[rg][nb][3] + bb1, 0.f));
                    const int nch = (n0 >> 3) + nb;
                    *reinterpret_cast<uint32_t*>(
                        sm + SM_H2 + rowa * 256 + ((nch ^ (rowa & 7)) * 16) + tig * 4) = p0;
                    *reinterpret_cast<uint32_t*>(
                        sm + SM_H2 + rowb * 256 + ((nch ^ (rowb & 7)) * 16) + tig * 4) = p1;
                }
            }
        }
        NAMED_BAR(barid);   // H2 rows of this group ready for this group

        // ---- Phase 2: H3 = H2 @ W3, fused column-max ----
        {
            uint32_t a[2][8][4];
            #pragma unroll
            for (int rg = 0; rg < 2; rg++)
                #pragma unroll
                for (int kb = 0; kb < 8; kb++) {
                    const int rr = r0 + rg * 16 + (lane & 15);
                    const int ch = (kb * 2 + (lane >> 4)) ^ (rr & 7);
                    ldsm_x4(a[rg][kb][0], a[rg][kb][1], a[rg][kb][2], a[rg][kb][3],
                            s0 + SM_H2 + rr * 256 + ch * 16);
                }
            #pragma unroll
            for (int tile = 0; tile < 2; tile++) {
                const int n0 = ct * 32 + tile * 128;
                float c[2][4][4] = {};
                #pragma unroll
                for (int kb = 0; kb < 8; kb++) {
                    const int krow = kb * 16 + (qh & 1) * 8 + ql;
                    #pragma unroll
                    for (int jp = 0; jp < 2; jp++) {
                        const int nch = (n0 >> 3) + jp * 2 + (qh >> 1);
                        uint32_t b0, b1, b2r, b3r;
                        ldsm_x4t(b0, b1, b2r, b3r,
                                 s0 + SM_W3 + krow * 512 + ((nch ^ (krow & 7)) * 16));
                        mma16816(c[0][jp * 2],     a[0][kb], b0, b1);
                        mma16816(c[1][jp * 2],     a[1][kb], b0, b1);
                        mma16816(c[0][jp * 2 + 1], a[0][kb], b2r, b3r);
                        mma16816(c[1][jp * 2 + 1], a[1][kb], b2r, b3r);
                    }
                }
                #pragma unroll
                for (int nb = 0; nb < 4; nb++) {
                    float m0 = fmaxf(fmaxf(c[0][nb][0], c[0][nb][2]),
                                     fmaxf(c[1][nb][0], c[1][nb][2]));
                    float m1 = fmaxf(fmaxf(c[0][nb][1], c[0][nb][3]),
                                     fmaxf(c[1][nb][1], c[1][nb][3]));
                    #pragma unroll
                    for (int off = 4; off < 32; off <<= 1) {
                        m0 = fmaxf(m0, __shfl_xor_sync(0xffffffff, m0, off));
                        m1 = fmaxf(m1, __shfl_xor_sync(0xffffffff, m1, off));
                    }
                    if (lane < 4) {
                        sPart[rt * 256 + n0 + nb * 8 + 2 * tig]     = m0;
                        sPart[rt * 256 + n0 + nb * 8 + 2 * tig + 1] = m1;
                    }
                }
            }
        }
        __syncthreads();    // cross-group: sPart complete

        if (tid < 256) {
            const float v = fmaxf(fmaxf(sPart[tid], sPart[256 + tid]),
                                  fmaxf(sPart[512 + tid], sPart[768 + tid]));
            feat_out[(size_t)obj * 256 + tid] = v + sB3f[tid];
        }
        pb ^= 1;   // double-buffered sPart: next object's writes can't clobber reads
    }
}

// ============================== sgnet mma GEMM (128-row tiles) ==============================
template <bool GATHER, bool RELU, bool IN_F16, bool OUT_F16, int NPAD>
__global__ __launch_bounds__(512) void mma_gemm(
    const void* __restrict__ Ain,
    const float* __restrict__ Asrc, const float* __restrict__ Aref,
    const float* __restrict__ W, const float* __restrict__ bias,
    void* __restrict__ Cout, int nmax, int ldc, int coff)
{
    extern __shared__ char sm[];
    const uint32_t s0 = smem_u32(sm);
    char* sA = sm;                         // 128 x 512B
    char* sW = sm + 65536;                 // 256 x (NPAD*2)B
    float* sBias = reinterpret_cast<float*>(sW + 256 * NPAD * 2);

    const int tid = threadIdx.x;
    const int wid = tid >> 5, lane = tid & 31;
    const int m0 = blockIdx.x * 128;

    // ---- Stage A tile (f16, swizzled; rowBytes = 512) ----
    {
        const int r = tid >> 2, q = tid & 3;
        const int m = m0 + r;
        if (IN_F16) {
            const __half* arow = reinterpret_cast<const __half*>(Ain) + (size_t)m * 256;
            #pragma unroll
            for (int e = 0; e < 8; e++) {
                const int c = q * 8 + e;
                uint4 u = *reinterpret_cast<const uint4*>(arow + c * 8);
                *reinterpret_cast<uint4*>(sA + r * 512 + ((c ^ (r & 7)) * 16)) = u;
            }
        } else {
            const float* arow;
            if (GATHER) {
                const int b = m >> 10, j = m & 1023;
                arow = (j < 512) ? (Asrc + (size_t)(b * 512 + j) * 256)
                                 : (Aref + (size_t)(b * 512 + (j - 512)) * 256);
            } else {
                arow = reinterpret_cast<const float*>(Ain) + (size_t)m * 256;
            }
            #pragma unroll
            for (int e = 0; e < 8; e++) {
                const int c = q * 8 + e;
                float4 f0 = *reinterpret_cast<const float4*>(arow + c * 8);
                float4 f1 = *reinterpret_cast<const float4*>(arow + c * 8 + 4);
                uint4 u = make_uint4(pack2(f0.x, f0.y), pack2(f0.z, f0.w),
                                     pack2(f1.x, f1.y), pack2(f1.z, f1.w));
                *reinterpret_cast<uint4*>(sA + r * 512 + ((c ^ (r & 7)) * 16)) = u;
            }
        }
    }
    // ---- Stage W (256 x NPAD f16, swizzled) ----
    {
        const int r = tid >> 1, h = tid & 1;
        const int CH = NPAD / 16;       // 16B chunks per half-row job
        #pragma unroll
        for (int e = 0; e < CH; e++) {
            const int c = h * CH + e;
            uint4 u;
            if (NPAD == 256) {
                float4 f0 = *reinterpret_cast<const float4*>(W + (size_t)r * nmax + c * 8);
                float4 f1 = *reinterpret_cast<const float4*>(W + (size_t)r * nmax + c * 8 + 4);
                u = make_uint4(pack2(f0.x, f0.y), pack2(f0.z, f0.w),
                               pack2(f1.x, f1.y), pack2(f1.z, f1.w));
            } else {
                float v[8];
                #pragma unroll
                for (int i = 0; i < 8; i++) {
                    const int col = c * 8 + i;
                    v[i] = (col < nmax) ? W[(size_t)r * nmax + col] : 0.f;
                }
                u = make_uint4(pack2(v[0], v[1]), pack2(v[2], v[3]),
                               pack2(v[4], v[5]), pack2(v[6], v[7]));
            }
            *reinterpret_cast<uint4*>(sW + r * (NPAD * 2) + ((c ^ (r & 7)) * 16)) = u;
        }
    }
    if (tid < NPAD) sBias[tid] = (tid < nmax) ? bias[tid] : 0.f;
    __syncthreads();

    // ---- Compute: warp (rt, ct); warp tile 32 x (NPAD/4) ----
    const int g = lane >> 2, tig = lane & 3;
    const int rt = wid >> 2, ct = wid & 3;
    const int r0 = rt * 32;
    const int NJ = NPAD / 32;
    const int n0 = ct * (NPAD / 4);

    float c[2][NPAD / 32][4];
    #pragma unroll
    for (int rg = 0; rg < 2; rg++)
        #pragma unroll
        for (int j = 0; j < NJ; j++)
            #pragma unroll
            for (int e = 0; e < 4; e++) c[rg][j][e] = 0.f;

    const uint32_t wRowB = NPAD * 2;
    #pragma unroll
    for (int kb = 0; kb < 16; kb++) {
        uint32_t a[2][4];
        #pragma unroll
        for (int rg = 0; rg < 2; rg++) {
            const int rr = r0 + rg * 16 + (lane & 15);
            const int ch = (kb * 2 + (lane >> 4)) ^ (rr & 7);
            ldsm_x4(a[rg][0], a[rg][1], a[rg][2], a[rg][3],
                    s0 + rr * 512 + ch * 16);
        }
        const int krow = kb * 16 + (lane & 15);
        #pragma unroll
        for (int j = 0; j < NJ; j++) {
            const int nch = (n0 >> 3) + j;
            uint32_t b0, b1;
            ldsm_x2t(b0, b1, s0 + 65536 + krow * wRowB + ((nch ^ (krow & 7)) * 16));
            mma16816(c[0][j], a[0], b0, b1);
            mma16816(c[1][j], a[1], b0, b1);
        }
    }

    // ---- Epilogue ----
    #pragma unroll
    for (int rg = 0; rg < 2; rg++) {
        const int rowa = m0 + r0 + rg * 16 + g;
        #pragma unroll
        for (int j = 0; j < NJ; j++) {
            const int col = n0 + j * 8 + 2 * tig;
            float v0 = c[rg][j][0] + sBias[col];
            float v1 = c[rg][j][1] + sBias[col + 1];
            float v2 = c[rg][j][2] + sBias[col];
            float v3 = c[rg][j][3] + sBias[col + 1];
            if (RELU) {
                v0 = fmaxf(v0, 0.f); v1 = fmaxf(v1, 0.f);
                v2 = fmaxf(v2, 0.f); v3 = fmaxf(v3, 0.f);
            }
            if (OUT_F16) {
                __half* y = reinterpret_cast<__half*>(Cout);
                *reinterpret_cast<uint32_t*>(y + (size_t)rowa * 256 + col) = pack2(v0, v1);
                *reinterpret_cast<uint32_t*>(y + (size_t)(rowa + 8) * 256 + col) = pack2(v2, v3);
            } else {
                float* o = reinterpret_cast<float*>(Cout);
                if (col < nmax) {
                    o[(size_t)rowa * ldc + coff + col] = v0;
                    o[(size_t)(rowa + 8) * ldc + coff + col] = v2;
                }
                if (col + 1 < nmax) {
                    o[(size_t)rowa * ldc + coff + col + 1] = v1;
                    o[(size_t)(rowa + 8) * ldc + coff + col + 1] = v3;
                }
            }
        }
    }
}

// ============================== Launch ==============================
extern "C" void kernel_launch(void* const* d_in, const int* in_sizes, int n_in,
                              void* d_out, int out_size)
{
    const float* tot_obj_pts = (const float*)d_in[0];
    const float* src_feat    = (const float*)d_in[1];
    const float* ref_feat    = (const float*)d_in[2];
    const float* sg_w1 = (const float*)d_in[6];
    const float* sg_b1 = (const float*)d_in[7];
    const float* sg_w2 = (const float*)d_in[8];
    const float* sg_b2 = (const float*)d_in[9];
    const float* se_w  = (const float*)d_in[10];
    const float* se_b  = (const float*)d_in[11];
    const float* p_w1  = (const float*)d_in[12];
    const float* p_b1  = (const float*)d_in[13];
    const float* p_w2  = (const float*)d_in[14];
    const float* p_b2  = (const float*)d_in[15];
    const float* p_w3  = (const float*)d_in[16];
    const float* p_b3  = (const float*)d_in[17];
    const float* oe_w  = (const float*)d_in[18];
    const float* oe_b  = (const float*)d_in[19];
    float* out = (float*)d_out;

    void *ph1, *ph2, *pfeat;
    cudaGetSymbolAddress(&ph1, g_h1);
    cudaGetSymbolAddress(&ph2, g_h2);
    cudaGetSymbolAddress(&pfeat, g_feat);

    int sms = 148;
    cudaDeviceGetAttribute(&sms, cudaDevAttrMultiProcessorCount, 0);

    cudaFuncSetAttribute(pointnet_mma,
                         cudaFuncAttributeMaxDynamicSharedMemorySize, SM_TOTAL);

    // PointNet branch (dominant)
    pointnet_mma<<<sms, 512, SM_TOTAL>>>(
        tot_obj_pts, p_w1, p_b1, p_w2, p_b2, p_w3, p_b3, (float*)pfeat, NTOT);

    // sgnet chain on tensor cores
    const int SMEM_256 = 65536 + 131072 + 1024;   // 197632
    const int SMEM_128 = 65536 + 65536 + 512;     // 131584

    auto k1 = mma_gemm<true,  true,  false, true, 256>;
    auto k2 = mma_gemm<false, false, true,  true, 256>;
    auto k3 = mma_gemm<false, false, true,  false, 128>;
    auto k4 = mma_gemm<false, false, false, false, 128>;
    cudaFuncSetAttribute(k1, cudaFuncAttributeMaxDynamicSharedMemorySize, SMEM_256);
    cudaFuncSetAttribute(k2, cudaFuncAttributeMaxDynamicSharedMemorySize, SMEM_256);
    cudaFuncSetAttribute(k3, cudaFuncAttributeMaxDynamicSharedMemorySize, SMEM_128);
    cudaFuncSetAttribute(k4, cudaFuncAttributeMaxDynamicSharedMemorySize, SMEM_128);

    // h1 = relu(gather(src,ref) @ sg_w1 + sg_b1)
    k1<<<NTOT / 128, 512, SMEM_256>>>(nullptr, src_feat, ref_feat,
                                      sg_w1, sg_b1, ph1, 256, 0, 0);
    // h2 = h1 @ sg_w2 + sg_b2
    k2<<<NTOT / 128, 512, SMEM_256>>>(ph1, nullptr, nullptr,
                                      sg_w2, sg_b2, ph2, 256, 0, 0);
    // out[:, 0:100] = h2 @ se_w + se_b
    k3<<<NTOT / 128, 512, SMEM_128>>>(ph2, nullptr, nullptr,
                                      se_w, se_b, out, EMB, 200, 0);
    // out[:, 100:200] = feat @ oe_w + oe_b
    k4<<<NTOT / 128, 512, SMEM_128>>>(pfeat, nullptr, nullptr,
                                      oe_w, oe_b, out, EMB, 200, 100);
}

// round 8
// speedup vs baseline: 6.2558x; 1.0130x over previous
#include <cuda_runtime.h>
#include <cuda_fp16.h>
#include <cstdint>

#define NTOT 16384
#define EMB  100

// Scratch (device globals — no runtime allocation allowed).
__device__ __half g_h1[NTOT * 256];      // relu(gather@sg_w1+b1), f16
__device__ __half g_h2[NTOT * 256];      // h1@sg_w2+b2, f16
__device__ float  g_feat[4 * NTOT * 256]; // per-group partial col-max (+b3)

// ============================== helpers ==============================
__device__ __forceinline__ uint32_t smem_u32(const void* p) {
    uint32_t a;
    asm("{ .reg .u64 t; cvta.to.shared.u64 t, %1; cvt.u32.u64 %0, t; }"
        : "=r"(a) : "l"(p));
    return a;
}
__device__ __forceinline__ uint32_t pack2(float lo, float hi) {
    __half2 h = __floats2half2_rn(lo, hi);
    return *reinterpret_cast<uint32_t*>(&h);
}
__device__ __forceinline__ void ldsm_x4(uint32_t& r0, uint32_t& r1, uint32_t& r2, uint32_t& r3,
                                        uint32_t addr) {
    asm volatile("ldmatrix.sync.aligned.m8n8.x4.shared.b16 {%0,%1,%2,%3}, [%4];"
                 : "=r"(r0), "=r"(r1), "=r"(r2), "=r"(r3) : "r"(addr));
}
__device__ __forceinline__ void ldsm_x2t(uint32_t& r0, uint32_t& r1, uint32_t addr) {
    asm volatile("ldmatrix.sync.aligned.m8n8.x2.trans.shared.b16 {%0,%1}, [%2];"
                 : "=r"(r0), "=r"(r1) : "r"(addr));
}
__device__ __forceinline__ void ldsm_x4t(uint32_t& r0, uint32_t& r1, uint32_t& r2, uint32_t& r3,
                                         uint32_t addr) {
    asm volatile("ldmatrix.sync.aligned.m8n8.x4.trans.shared.b16 {%0,%1,%2,%3}, [%4];"
                 : "=r"(r0), "=r"(r1), "=r"(r2), "=r"(r3) : "r"(addr));
}
__device__ __forceinline__ void mma16816(float* c, const uint32_t* a, uint32_t b0, uint32_t b1) {
    asm volatile("mma.sync.aligned.m16n8k16.row.col.f32.f16.f16.f32 "
                 "{%0,%1,%2,%3}, {%4,%5,%6,%7}, {%8,%9}, {%0,%1,%2,%3};"
                 : "+f"(c[0]), "+f"(c[1]), "+f"(c[2]), "+f"(c[3])
                 : "r"(a[0]), "r"(a[1]), "r"(a[2]), "r"(a[3]), "r"(b0), "r"(b1));
}
#define NAMED_BAR(id) \
    asm volatile("bar.sync %0, 128;" :: "r"(id) : "memory")

// ============================== PointNet (mma.sync f16) ==============================
// SMEM byte offsets
#define SM_W3   0        /* 128 x 512B  (f16, swizzled)  = 65536 */
#define SM_W2   65536    /* 64  x 256B                    = 16384 */
#define SM_H2   81920    /* 128 x 256B                    = 32768 */
#define SM_H1   114688   /* 128 x 128B                    = 16384 */
#define SM_B2   131072   /* 128 f32 */
#define SM_B3   131584   /* 256 f32 */
#define SM_W1   132608   /* 192 f32 */
#define SM_B1   133376   /* 64  f32 */
#define SM_TOTAL 133632

__global__ __launch_bounds__(512, 1) void pointnet_mma(
    const float* __restrict__ pts,
    const float* __restrict__ w1, const float* __restrict__ b1,
    const float* __restrict__ w2, const float* __restrict__ b2,
    const float* __restrict__ w3, const float* __restrict__ b3,
    float* __restrict__ featp, int ntot)
{
    extern __shared__ char sm[];
    const uint32_t s0 = smem_u32(sm);
    const int tid = threadIdx.x;
    const int wid = tid >> 5, lane = tid & 31;

    // ---- Stage weights (once per block) ----
    for (int i = tid * 8; i < 128 * 256; i += 512 * 8) {
        int k = i >> 8, n = i & 255;
        float4 f0 = *reinterpret_cast<const float4*>(w3 + i);
        float4 f1 = *reinterpret_cast<const float4*>(w3 + i + 4);
        uint4 u = make_uint4(pack2(f0.x, f0.y), pack2(f0.z, f0.w),
                             pack2(f1.x, f1.y), pack2(f1.z, f1.w));
        int ch = (n >> 3) ^ (k & 7);
        *reinterpret_cast<uint4*>(sm + SM_W3 + k * 512 + ch * 16) = u;
    }
    for (int i = tid * 8; i < 64 * 128; i += 512 * 8) {
        int k = i >> 7, n = i & 127;
        float4 f0 = *reinterpret_cast<const float4*>(w2 + i);
        float4 f1 = *reinterpret_cast<const float4*>(w2 + i + 4);
        uint4 u = make_uint4(pack2(f0.x, f0.y), pack2(f0.z, f0.w),
                             pack2(f1.x, f1.y), pack2(f1.z, f1.w));
        int ch = (n >> 3) ^ (k & 7);
        *reinterpret_cast<uint4*>(sm + SM_W2 + k * 256 + ch * 16) = u;
    }
    if (tid < 128) reinterpret_cast<float*>(sm + SM_B2)[tid] = b2[tid];
    if (tid < 256) reinterpret_cast<float*>(sm + SM_B3)[tid] = b3[tid];
    if (tid < 192) reinterpret_cast<float*>(sm + SM_W1)[tid] = w1[tid];
    if (tid < 64)  reinterpret_cast<float*>(sm + SM_B1)[tid] = b1[tid];
    __syncthreads();   // only block-wide sync in the whole kernel

    const float* sW1f = reinterpret_cast<const float*>(sm + SM_W1);
    const float* sB1f = reinterpret_cast<const float*>(sm + SM_B1);
    const float* sB2f = reinterpret_cast<const float*>(sm + SM_B2);
    const float* sB3f = reinterpret_cast<const float*>(sm + SM_B3);

    const int g = lane >> 2, tig = lane & 3;
    const int rt = wid >> 2, ct = wid & 3;
    const int r0 = rt * 32;
    const int row = tid >> 2, q = tid & 3;
    const int barid = 1 + rt;           // named barrier per 4-warp group
    const int qh = lane >> 3;           // quad for x4t addressing
    const int ql = lane & 7;

    // Prefetch first object's coords
    float nx0 = 0.f, nx1 = 0.f, nx2 = 0.f;
    if (blockIdx.x < (unsigned)ntot) {
        const float* pr = pts + (size_t)blockIdx.x * 384 + row * 3;
        nx0 = pr[0]; nx1 = pr[1]; nx2 = pr[2];
    }

    for (int obj = blockIdx.x; obj < ntot; obj += gridDim.x) {
        // ---- H1 = relu(pts@W1 + b1) -> sH1 rows [32rt, 32rt+32) ----
        {
            const float x0 = nx0, x1 = nx1, x2 = nx2;
            uint32_t u[8];
            #pragma unroll
            for (int e = 0; e < 8; e++) {
                const int c0 = q * 16 + e * 2;
                float v0 = fmaf(x2, sW1f[128 + c0],
                           fmaf(x1, sW1f[64 + c0], fmaf(x0, sW1f[c0], sB1f[c0])));
                float v1 = fmaf(x2, sW1f[129 + c0],
                           fmaf(x1, sW1f[65 + c0], fmaf(x0, sW1f[c0 + 1], sB1f[c0 + 1])));
                u[e] = pack2(fmaxf(v0, 0.f), fmaxf(v1, 0.f));
            }
            const int ch0 = (q * 2) ^ (row & 7), ch1 = (q * 2 + 1) ^ (row & 7);
            *reinterpret_cast<uint4*>(sm + SM_H1 + row * 128 + ch0 * 16) =
                make_uint4(u[0], u[1], u[2], u[3]);
            *reinterpret_cast<uint4*>(sm + SM_H1 + row * 128 + ch1 * 16) =
                make_uint4(u[4], u[5], u[6], u[7]);
            // Prefetch next object's coords
            const int nobj = obj + gridDim.x;
            if (nobj < ntot) {
                const float* pr = pts + (size_t)nobj * 384 + row * 3;
                nx0 = pr[0]; nx1 = pr[1]; nx2 = pr[2];
            }
        }
        NAMED_BAR(barid);   // group's H1 rows ready

        // ---- Phase 1: H2 rows [32rt..) = relu(H1 @ W2 + b2), warp tile 32x32 ----
        {
            const int n0 = ct * 32;
            uint32_t a[2][4][4];
            #pragma unroll
            for (int rg = 0; rg < 2; rg++)
                #pragma unroll
                for (int kb = 0; kb < 4; kb++) {
                    const int rr = r0 + rg * 16 + (lane & 15);
                    const int ch = (kb * 2 + (lane >> 4)) ^ (rr & 7);
                    ldsm_x4(a[rg][kb][0], a[rg][kb][1], a[rg][kb][2], a[rg][kb][3],
                            s0 + SM_H1 + rr * 128 + ch * 16);
                }
            float c[2][4][4] = {};
            #pragma unroll
            for (int kb = 0; kb < 4; kb++) {
                const int krow = kb * 16 + (qh & 1) * 8 + ql;
                #pragma unroll
                for (int jp = 0; jp < 2; jp++) {
                    const int nch = (n0 >> 3) + jp * 2 + (qh >> 1);
                    uint32_t b0, b1, b2r, b3r;
                    ldsm_x4t(b0, b1, b2r, b3r,
                             s0 + SM_W2 + krow * 256 + ((nch ^ (krow & 7)) * 16));
                    mma16816(c[0][jp * 2],     a[0][kb], b0, b1);
                    mma16816(c[1][jp * 2],     a[1][kb], b0, b1);
                    mma16816(c[0][jp * 2 + 1], a[0][kb], b2r, b3r);
                    mma16816(c[1][jp * 2 + 1], a[1][kb], b2r, b3r);
                }
            }
            #pragma unroll
            for (int rg = 0; rg < 2; rg++) {
                const int rowa = r0 + rg * 16 + g, rowb = rowa + 8;
                #pragma unroll
                for (int nb = 0; nb < 4; nb++) {
                    const int col = n0 + nb * 8 + 2 * tig;
                    const float bb0 = sB2f[col], bb1 = sB2f[col + 1];
                    const uint32_t p0 = pack2(fmaxf(c[rg][nb][0] + bb0, 0.f),
                                              fmaxf(c[rg][nb][1] + bb1, 0.f));
                    const uint32_t p1 = pack2(fmaxf(c[rg][nb][2] + bb0, 0.f),
                                              fmaxf(c[rg][nb][3] + bb1, 0.f));
                    const int nch = (n0 >> 3) + nb;
                    *reinterpret_cast<uint32_t*>(
                        sm + SM_H2 + rowa * 256 + ((nch ^ (rowa & 7)) * 16) + tig * 4) = p0;
                    *reinterpret_cast<uint32_t*>(
                        sm + SM_H2 + rowb * 256 + ((nch ^ (rowb & 7)) * 16) + tig * 4) = p1;
                }
            }
        }
        NAMED_BAR(barid);   // group's H2 rows ready

        // ---- Phase 2: H3 rows = H2 @ W3; partial col-max over the group's 32 rows ----
        {
            uint32_t a[2][8][4];
            #pragma unroll
            for (int rg = 0; rg < 2; rg++)
                #pragma unroll
                for (int kb = 0; kb < 8; kb++) {
                    const int rr = r0 + rg * 16 + (lane & 15);
                    const int ch = (kb * 2 + (lane >> 4)) ^ (rr & 7);
                    ldsm_x4(a[rg][kb][0], a[rg][kb][1], a[rg][kb][2], a[rg][kb][3],
                            s0 + SM_H2 + rr * 256 + ch * 16);
                }
            float* outp = featp + ((size_t)rt * NTOT + obj) * 256;
            #pragma unroll
            for (int tile = 0; tile < 2; tile++) {
                const int n0 = ct * 32 + tile * 128;
                float c[2][4][4] = {};
                #pragma unroll
                for (int kb = 0; kb < 8; kb++) {
                    const int krow = kb * 16 + (qh & 1) * 8 + ql;
                    #pragma unroll
                    for (int jp = 0; jp < 2; jp++) {
                        const int nch = (n0 >> 3) + jp * 2 + (qh >> 1);
                        uint32_t b0, b1, b2r, b3r;
                        ldsm_x4t(b0, b1, b2r, b3r,
                                 s0 + SM_W3 + krow * 512 + ((nch ^ (krow & 7)) * 16));
                        mma16816(c[0][jp * 2],     a[0][kb], b0, b1);
                        mma16816(c[1][jp * 2],     a[1][kb], b0, b1);
                        mma16816(c[0][jp * 2 + 1], a[0][kb], b2r, b3r);
                        mma16816(c[1][jp * 2 + 1], a[1][kb], b2r, b3r);
                    }
                }
                #pragma unroll
                for (int nb = 0; nb < 4; nb++) {
                    float m0 = fmaxf(fmaxf(c[0][nb][0], c[0][nb][2]),
                                     fmaxf(c[1][nb][0], c[1][nb][2]));
                    float m1 = fmaxf(fmaxf(c[0][nb][1], c[0][nb][3]),
                                     fmaxf(c[1][nb][1], c[1][nb][3]));
                    #pragma unroll
                    for (int off = 4; off < 32; off <<= 1) {
                        m0 = fmaxf(m0, __shfl_xor_sync(0xffffffff, m0, off));
                        m1 = fmaxf(m1, __shfl_xor_sync(0xffffffff, m1, off));
                    }
                    if (lane < 4) {
                        const int col = n0 + nb * 8 + 2 * tig;
                        float2 v = make_float2(m0 + sB3f[col], m1 + sB3f[col + 1]);
                        *reinterpret_cast<float2*>(outp + col) = v;
                    }
                }
            }
        }
        // no block-wide sync: groups drift freely; cross-group max happens in k4.
    }
}

// ============================== sgnet mma GEMM (128-row tiles) ==============================
// MAXG: A row m = max over 4 partial buffers (pointnet group partials).
template <bool GATHER, bool RELU, bool IN_F16, bool OUT_F16, bool MAXG, int NPAD>
__global__ __launch_bounds__(512) void mma_gemm(
    const void* __restrict__ Ain,
    const float* __restrict__ Asrc, const float* __restrict__ Aref,
    const float* __restrict__ W, const float* __restrict__ bias,
    void* __restrict__ Cout, int nmax, int ldc, int coff)
{
    extern __shared__ char sm[];
    const uint32_t s0 = smem_u32(sm);
    char* sA = sm;                         // 128 x 512B
    char* sW = sm + 65536;                 // 256 x (NPAD*2)B
    float* sBias = reinterpret_cast<float*>(sW + 256 * NPAD * 2);

    const int tid = threadIdx.x;
    const int wid = tid >> 5, lane = tid & 31;
    const int m0 = blockIdx.x * 128;

    // ---- Stage A tile (f16, swizzled; rowBytes = 512) ----
    {
        const int r = tid >> 2, q = tid & 3;
        const int m = m0 + r;
        if (IN_F16) {
            const __half* arow = reinterpret_cast<const __half*>(Ain) + (size_t)m * 256;
            #pragma unroll
            for (int e = 0; e < 8; e++) {
                const int c = q * 8 + e;
                uint4 u = *reinterpret_cast<const uint4*>(arow + c * 8);
                *reinterpret_cast<uint4*>(sA + r * 512 + ((c ^ (r & 7)) * 16)) = u;
            }
        } else if (MAXG) {
            const float* arow = reinterpret_cast<const float*>(Ain) + (size_t)m * 256;
            #pragma unroll
            for (int e = 0; e < 8; e++) {
                const int c = q * 8 + e;
                float4 f0 = *reinterpret_cast<const float4*>(arow + c * 8);
                float4 f1 = *reinterpret_cast<const float4*>(arow + c * 8 + 4);
                #pragma unroll
                for (int p = 1; p < 4; p++) {
                    const float* ar = arow + (size_t)p * NTOT * 256;
                    float4 g0 = *reinterpret_cast<const float4*>(ar + c * 8);
                    float4 g1 = *reinterpret_cast<const float4*>(ar + c * 8 + 4);
                    f0.x = fmaxf(f0.x, g0.x); f0.y = fmaxf(f0.y, g0.y);
                    f0.z = fmaxf(f0.z, g0.z); f0.w = fmaxf(f0.w, g0.w);
                    f1.x = fmaxf(f1.x, g1.x); f1.y = fmaxf(f1.y, g1.y);
                    f1.z = fmaxf(f1.z, g1.z); f1.w = fmaxf(f1.w, g1.w);
                }
                uint4 u = make_uint4(pack2(f0.x, f0.y), pack2(f0.z, f0.w),
                                     pack2(f1.x, f1.y), pack2(f1.z, f1.w));
                *reinterpret_cast<uint4*>(sA + r * 512 + ((c ^ (r & 7)) * 16)) = u;
            }
        } else {
            const float* arow;
            if (GATHER) {
                const int b = m >> 10, j = m & 1023;
                arow = (j < 512) ? (Asrc + (size_t)(b * 512 + j) * 256)
                                 : (Aref + (size_t)(b * 512 + (j - 512)) * 256);
            } else {
                arow = reinterpret_cast<const float*>(Ain) + (size_t)m * 256;
            }
            #pragma unroll
            for (int e = 0; e < 8; e++) {
                const int c = q * 8 + e;
                float4 f0 = *reinterpret_cast<const float4*>(arow + c * 8);
                float4 f1 = *reinterpret_cast<const float4*>(arow + c * 8 + 4);
                uint4 u = make_uint4(pack2(f0.x, f0.y), pack2(f0.z, f0.w),
                                     pack2(f1.x, f1.y), pack2(f1.z, f1.w));
                *reinterpret_cast<uint4*>(sA + r * 512 + ((c ^ (r & 7)) * 16)) = u;
            }
        }
    }
    // ---- Stage W (256 x NPAD f16, swizzled) ----
    {
        const int r = tid >> 1, h = tid & 1;
        const int CH = NPAD / 16;       // 16B chunks per half-row job
        #pragma unroll
        for (int e = 0; e < CH; e++) {
            const int c = h * CH + e;
            uint4 u;
            if (NPAD == 256) {
                float4 f0 = *reinterpret_cast<const float4*>(W + (size_t)r * nmax + c * 8);
                float4 f1 = *reinterpret_cast<const float4*>(W + (size_t)r * nmax + c * 8 + 4);
                u = make_uint4(pack2(f0.x, f0.y), pack2(f0.z, f0.w),
                               pack2(f1.x, f1.y), pack2(f1.z, f1.w));
            } else {
                float v[8];
                #pragma unroll
                for (int i = 0; i < 8; i++) {
                    const int col = c * 8 + i;
                    v[i] = (col < nmax) ? W[(size_t)r * nmax + col] : 0.f;
                }
                u = make_uint4(pack2(v[0], v[1]), pack2(v[2], v[3]),
                               pack2(v[4], v[5]), pack2(v[6], v[7]));
            }
            *reinterpret_cast<uint4*>(sW + r * (NPAD * 2) + ((c ^ (r & 7)) * 16)) = u;
        }
    }
    if (tid < NPAD) sBias[tid] = (tid < nmax) ? bias[tid] : 0.f;
    __syncthreads();

    // ---- Compute: warp (rt, ct); warp tile 32 x (NPAD/4) ----
    const int g = lane >> 2, tig = lane & 3;
    const int rt = wid >> 2, ct = wid & 3;
    const int r0 = rt * 32;
    const int NJ = NPAD / 32;
    const int n0 = ct * (NPAD / 4);

    float c[2][NPAD / 32][4];
    #pragma unroll
    for (int rg = 0; rg < 2; rg++)
        #pragma unroll
        for (int j = 0; j < NJ; j++)
            #pragma unroll
            for (int e = 0; e < 4; e++) c[rg][j][e] = 0.f;

    const uint32_t wRowB = NPAD * 2;
    #pragma unroll
    for (int kb = 0; kb < 16; kb++) {
        uint32_t a[2][4];
        #pragma unroll
        for (int rg = 0; rg < 2; rg++) {
            const int rr = r0 + rg * 16 + (lane & 15);
            const int ch = (kb * 2 + (lane >> 4)) ^ (rr & 7);
            ldsm_x4(a[rg][0], a[rg][1], a[rg][2], a[rg][3],
                    s0 + rr * 512 + ch * 16);
        }
        const int krow = kb * 16 + (lane & 15);
        #pragma unroll
        for (int j = 0; j < NJ; j++) {
            const int nch = (n0 >> 3) + j;
            uint32_t b0, b1;
            ldsm_x2t(b0, b1, s0 + 65536 + krow * wRowB + ((nch ^ (krow & 7)) * 16));
            mma16816(c[0][j], a[0], b0, b1);
            mma16816(c[1][j], a[1], b0, b1);
        }
    }

    // ---- Epilogue ----
    #pragma unroll
    for (int rg = 0; rg < 2; rg++) {
        const int rowa = m0 + r0 + rg * 16 + g;
        #pragma unroll
        for (int j = 0; j < NJ; j++) {
            const int col = n0 + j * 8 + 2 * tig;
            float v0 = c[rg][j][0] + sBias[col];
            float v1 = c[rg][j][1] + sBias[col + 1];
            float v2 = c[rg][j][2] + sBias[col];
            float v3 = c[rg][j][3] + sBias[col + 1];
            if (RELU) {
                v0 = fmaxf(v0, 0.f); v1 = fmaxf(v1, 0.f);
                v2 = fmaxf(v2, 0.f); v3 = fmaxf(v3, 0.f);
            }
            if (OUT_F16) {
                __half* y = reinterpret_cast<__half*>(Cout);
                *reinterpret_cast<uint32_t*>(y + (size_t)rowa * 256 + col) = pack2(v0, v1);
                *reinterpret_cast<uint32_t*>(y + (size_t)(rowa + 8) * 256 + col) = pack2(v2, v3);
            } else {
                float* o = reinterpret_cast<float*>(Cout);
                if (col < nmax) {
                    o[(size_t)rowa * ldc + coff + col] = v0;
                    o[(size_t)(rowa + 8) * ldc + coff + col] = v2;
                }
                if (col + 1 < nmax) {
                    o[(size_t)rowa * ldc + coff + col + 1] = v1;
                    o[(size_t)(rowa + 8) * ldc + coff + col + 1] = v3;
                }
            }
        }
    }
}

// ============================== Launch ==============================
extern "C" void kernel_launch(void* const* d_in, const int* in_sizes, int n_in,
                              void* d_out, int out_size)
{
    const float* tot_obj_pts = (const float*)d_in[0];
    const float* src_feat    = (const float*)d_in[1];
    const float* ref_feat    = (const float*)d_in[2];
    const float* sg_w1 = (const float*)d_in[6];
    const float* sg_b1 = (const float*)d_in[7];
    const float* sg_w2 = (const float*)d_in[8];
    const float* sg_b2 = (const float*)d_in[9];
    const float* se_w  = (const float*)d_in[10];
    const float* se_b  = (const float*)d_in[11];
    const float* p_w1  = (const float*)d_in[12];
    const float* p_b1  = (const float*)d_in[13];
    const float* p_w2  = (const float*)d_in[14];
    const float* p_b2  = (const float*)d_in[15];
    const float* p_w3  = (const float*)d_in[16];
    const float* p_b3  = (const float*)d_in[17];
    const float* oe_w  = (const float*)d_in[18];
    const float* oe_b  = (const float*)d_in[19];
    float* out = (float*)d_out;

    void *ph1, *ph2, *pfeat;
    cudaGetSymbolAddress(&ph1, g_h1);
    cudaGetSymbolAddress(&ph2, g_h2);
    cudaGetSymbolAddress(&pfeat, g_feat);

    int sms = 148;
    cudaDeviceGetAttribute(&sms, cudaDevAttrMultiProcessorCount, 0);

    cudaFuncSetAttribute(pointnet_mma,
                         cudaFuncAttributeMaxDynamicSharedMemorySize, SM_TOTAL);

    // PointNet branch (dominant) — writes 4 per-group partial max buffers
    pointnet_mma<<<sms, 512, SM_TOTAL>>>(
        tot_obj_pts, p_w1, p_b1, p_w2, p_b2, p_w3, p_b3, (float*)pfeat, NTOT);

    // sgnet chain on tensor cores
    const int SMEM_256 = 65536 + 131072 + 1024;   // 197632
    const int SMEM_128 = 65536 + 65536 + 512;     // 131584

    auto k1 = mma_gemm<true,  true,  false, true,  false, 256>;
    auto k2 = mma_gemm<false, false, true,  true,  false, 256>;
    auto k3 = mma_gemm<false, false, true,  false, false, 128>;
    auto k4 = mma_gemm<false, false, false, false, true,  128>;
    cudaFuncSetAttribute(k1, cudaFuncAttributeMaxDynamicSharedMemorySize, SMEM_256);
    cudaFuncSetAttribute(k2, cudaFuncAttributeMaxDynamicSharedMemorySize, SMEM_256);
    cudaFuncSetAttribute(k3, cudaFuncAttributeMaxDynamicSharedMemorySize, SMEM_128);
    cudaFuncSetAttribute(k4, cudaFuncAttributeMaxDynamicSharedMemorySize, SMEM_128);

    // h1 = relu(gather(src,ref) @ sg_w1 + sg_b1)
    k1<<<NTOT / 128, 512, SMEM_256>>>(nullptr, src_feat, ref_feat,
                                      sg_w1, sg_b1, ph1, 256, 0, 0);
    // h2 = h1 @ sg_w2 + sg_b2
    k2<<<NTOT / 128, 512, SMEM_256>>>(ph1, nullptr, nullptr,
                                      sg_w2, sg_b2, ph2, 256, 0, 0);
    // out[:, 0:100] = h2 @ se_w + se_b
    k3<<<NTOT / 128, 512, SMEM_128>>>(ph2, nullptr, nullptr,
                                      se_w, se_b, out, EMB, 200, 0);
    // out[:, 100:200] = max4(featp) @ oe_w + oe_b   (b3 already folded in)
    k4<<<NTOT / 128, 512, SMEM_128>>>(pfeat, nullptr, nullptr,
                                      oe_w, oe_b, out, EMB, 200, 100);
}